// round 10
// baseline (speedup 1.0000x reference)
#include <cuda_runtime.h>
#include <cstdint>

// ---------------------------------------------------------------------------
// CharacterEmbeddingLayer via vocabulary factorization + resident-weight head.
//  - conv: PP[char][piece][filter] precompute, conv = table adds + max,
//    tanh outside max (monotonic).  (exact R5 config, measured best)
//  - head: proj + 2 highway launches; weights staged ONCE per CTA into
//    XOR-swizzled smem (conflict-free LDS.128), tokens streamed through
//    double-buffered cp.async panels.
// ---------------------------------------------------------------------------

#define NTOK  25600      // 64*400 tokens

typedef unsigned long long u64;

// PP table: [13 filter-chunks][96 chars][14 pieces][8 filters]
__device__ float g_pp[13 * 96 * 14 * 8];
// conv outputs: [NTOK][400]
__device__ float g_outs[(size_t)NTOK * 400];
// head intermediates: [NTOK][128]
__device__ float g_x1[(size_t)NTOK * 128];
__device__ float g_x2[(size_t)NTOK * 128];

// ---------------- packed fp32x2 + async helpers -----------------------------
__device__ __forceinline__ void ffma2(u64 &acc, u64 a, u64 b) {
    asm("fma.rn.f32x2 %0, %1, %2, %0;" : "+l"(acc) : "l"(a), "l"(b));
}
__device__ __forceinline__ u64 fadd2(u64 a, u64 b) {
    u64 r; asm("add.rn.f32x2 %0, %1, %2;" : "=l"(r) : "l"(a), "l"(b)); return r;
}
__device__ __forceinline__ void unpack2(u64 v, float &lo, float &hi) {
    asm("mov.b64 {%0, %1}, %2;" : "=f"(lo), "=f"(hi) : "l"(v));
}
__device__ __forceinline__ float hadd2(u64 v) {
    float lo, hi; unpack2(v, lo, hi); return lo + hi;
}
__device__ __forceinline__ float tanh_fast(float x) {
    float y;
    asm("tanh.approx.f32 %0, %1;" : "=f"(y) : "f"(x));
    return y;
}
__device__ __forceinline__ uint32_t smem_u32(const void* p) {
    return (uint32_t)__cvta_generic_to_shared(p);
}
__device__ __forceinline__ void cp16(uint32_t dst, const void* src) {
    asm volatile("cp.async.ca.shared.global [%0], [%1], 16;" :: "r"(dst), "l"(src));
}
__device__ __forceinline__ void cp8(uint32_t dst, const void* src) {
    asm volatile("cp.async.ca.shared.global [%0], [%1], 8;" :: "r"(dst), "l"(src));
}
__device__ __forceinline__ void cp_commit() {
    asm volatile("cp.async.commit_group;");
}
template<int N> __device__ __forceinline__ void cp_wait() {
    asm volatile("cp.async.wait_group %0;" :: "n"(N));
}

// ---------------------------------------------------------------------------
// Kernel A: precompute PP.  grid = (96 chars, 14 pieces), 128 threads.
// ---------------------------------------------------------------------------
__global__ void pp_kernel(const float* __restrict__ cv,
                          const float* __restrict__ f2, const float* __restrict__ f3,
                          const float* __restrict__ f4, const float* __restrict__ f5)
{
    __shared__ float scv[64];
    const int c  = blockIdx.x;
    const int pg = blockIdx.y;
    const int j  = threadIdx.x;
    if (j < 64) scv[j] = __ldg(cv + c * 64 + j);
    __syncthreads();

    if (j < 104) {
        float s = 0.0f;
        if (j < 100) {
            const float* fp; int pl, RL;
            if (pg < 2)      { fp = f2; pl = pg;     RL = 2; }
            else if (pg < 5) { fp = f3; pl = pg - 2; RL = 3; }
            else if (pg < 9) { fp = f4; pl = pg - 5; RL = 4; }
            else             { fp = f5; pl = pg - 9; RL = 5; }
            const float4* fr = reinterpret_cast<const float4*>(fp + (j * RL + pl) * 64);
            #pragma unroll 4
            for (int q = 0; q < 16; q++) {
                const float4 fv = __ldg(fr + q);
                s += scv[4*q]   * fv.x + scv[4*q+1] * fv.y
                   + scv[4*q+2] * fv.z + scv[4*q+3] * fv.w;
            }
        }
        g_pp[(((j >> 3) * 96 + c) * 14 + pg) * 8 + (j & 7)] = s;
    }
}

// ---------------------------------------------------------------------------
// Kernel B: conv as table sums (exact R5 config).  grid = 400 (64 tok/CTA),
// 256 threads, 2 CTAs/SM. thread = (token t = tid>>2, filter-pair j2).
// ---------------------------------------------------------------------------
#define TB1  256
#define CHUNK_U64 (96 * 14 * 5)            // 6720 u64 per buffer
#define SMEMB_BYTES (2 * CHUNK_U64 * 8)    // 107520 B

__device__ __forceinline__ void stage_chunk(uint32_t sbuf,
                                            const float* __restrict__ src, int tid)
{
    #pragma unroll 1
    for (int i = tid; i < 5376; i += TB1) {       // 1344 rows x 4 u64
        const int r = i >> 2, e = i & 3;
        cp8(sbuf + (uint32_t)(r * 5 + e) * 8u, src + 2 * i);
    }
}

template<int W, int PB, int BOFF>
__device__ __forceinline__ void branch_sum(const u64* __restrict__ s_pp,
                                           const int (&bix)[16],
                                           float* __restrict__ orow,
                                           int g, int j2)
{
    constexpr int L = 17 - W;
    float m0 = -1e30f, m1 = -1e30f;
    #pragma unroll
    for (int l = 0; l < L; l++) {
        u64 a = s_pp[bix[l] + PB * 5];
        #pragma unroll
        for (int p = 1; p < W; p++)
            a = fadd2(a, s_pp[bix[l + p] + (PB + p) * 5]);
        float lo, hi; unpack2(a, lo, hi);
        m0 = fmaxf(m0, lo);
        m1 = fmaxf(m1, hi);
    }
    if (g < 12 || j2 < 2) {     // chunk 12: only filters 96..99 are real
        float2 r;
        r.x = tanh_fast(m0);
        r.y = tanh_fast(m1);
        *reinterpret_cast<float2*>(orow + BOFF + g * 8 + j2 * 2) = r;
    }
}

__global__ void __launch_bounds__(TB1, 2)
conv_sum_kernel(const int* __restrict__ idxs)
{
    extern __shared__ u64 s_pp2[];
    u64* buf0 = s_pp2;
    u64* buf1 = s_pp2 + CHUNK_U64;
    const uint32_t sb0 = smem_u32(buf0);
    const uint32_t sb1 = smem_u32(buf1);

    const int tid = threadIdx.x;
    const int j2  = tid & 3;
    const int token = blockIdx.x * 64 + (tid >> 2);

    int bix[16];
    {
        const int4* ip4 = reinterpret_cast<const int4*>(idxs + token * 16);
        const int4 A = __ldg(ip4 + 0), B = __ldg(ip4 + 1);
        const int4 C = __ldg(ip4 + 2), D = __ldg(ip4 + 3);
        bix[ 0] = A.x * 70 + j2; bix[ 1] = A.y * 70 + j2;
        bix[ 2] = A.z * 70 + j2; bix[ 3] = A.w * 70 + j2;
        bix[ 4] = B.x * 70 + j2; bix[ 5] = B.y * 70 + j2;
        bix[ 6] = B.z * 70 + j2; bix[ 7] = B.w * 70 + j2;
        bix[ 8] = C.x * 70 + j2; bix[ 9] = C.y * 70 + j2;
        bix[10] = C.z * 70 + j2; bix[11] = C.w * 70 + j2;
        bix[12] = D.x * 70 + j2; bix[13] = D.y * 70 + j2;
        bix[14] = D.z * 70 + j2; bix[15] = D.w * 70 + j2;
    }

    float* orow = g_outs + (size_t)token * 400;

    stage_chunk(sb0, g_pp, tid);
    cp_commit();

    #pragma unroll 1
    for (int g = 0; g < 13; g++) {
        if (g < 12) {
            stage_chunk((g & 1) ? sb0 : sb1, g_pp + (g + 1) * 10752, tid);
            cp_commit();
            cp_wait<1>();
        } else {
            cp_wait<0>();
        }
        __syncthreads();
        const u64* sp = (g & 1) ? buf1 : buf0;
        branch_sum<2, 0,   0>(sp, bix, orow, g, j2);
        branch_sum<3, 2, 100>(sp, bix, orow, g, j2);
        branch_sum<4, 5, 200>(sp, bix, orow, g, j2);
        branch_sum<5, 9, 300>(sp, bix, orow, g, j2);
        __syncthreads();                  // buffer g&1 free for restage
    }
}

// ---------------------------------------------------------------------------
// Kernel C1: projection (400->128, no bias), channel-split resident weights.
// grid (148, 2): blockIdx.y = channel half (64 channels), 512 threads,
// 1 CTA/SM.  Weight half staged ONCE into XOR-swizzled 128B atoms
// (atom row = s*64 + c, unit q' = q ^ (c&7)) -> conflict-free LDS.128.
// Tokens streamed in 32-token batches (double-buffered cp.async panels);
// batches strided b = blockIdx.x, b += 148, b < 800.
// ---------------------------------------------------------------------------
#define PJ_WF   (13 * 64 * 32)             // weight floats (atoms padded to 32f)
#define PJ_XU   101                        // float4 units per token row
#define PJ_XF   (32 * PJ_XU * 4)           // floats per x buffer (12928)
#define PJ_SMEM ((PJ_WF + 2 * PJ_XF) * 4)  // 209920 B

__global__ void __launch_bounds__(512, 1)
proj_kernel(const float* __restrict__ wp, float* __restrict__ xout)
{
    extern __shared__ float sm[];
    float* sw  = sm;                       // [13*64 atoms][32 floats]
    float* xb0 = sw + PJ_WF;
    float* xb1 = xb0 + PJ_XF;
    const uint32_t swb  = smem_u32(sw);
    const uint32_t xbb[2] = { smem_u32(xb0), smem_u32(xb1) };
    float* const xbf[2] = { xb0, xb1 };

    const int tid  = threadIdx.x;
    const int c    = tid & 63;             // channel within half
    const int slot = tid >> 6;             // 0..7, 4 tokens each
    const int h    = blockIdx.y;           // channel half

    // ---- stage weights once (valid units only; pad units never read) -----
    #pragma unroll 1
    for (int i = tid; i < 6400; i += 512) {
        int s, cc, q;
        if (i < 6144) { s = i >> 9; const int r = i & 511; cc = r >> 3; q = r & 7; }
        else          { const int j = i - 6144; s = 12; cc = j >> 2; q = j & 3; }
        const int dst = (s * 64 + cc) * 8 + (q ^ (cc & 7));
        cp16(swb + (uint32_t)dst * 16u, wp + (h * 64 + cc) * 400 + s * 32 + q * 4);
    }
    cp_commit();

    // ---- stream token batches --------------------------------------------
    auto stage_x = [&](int b, uint32_t xb) {
        const int tok0 = b * 32;
        #pragma unroll 1
        for (int i = tid; i < 3200; i += 512) {
            const int t = i / 100, u = i - t * 100;
            cp16(xb + (uint32_t)(t * PJ_XU + u) * 16u,
                 g_outs + (size_t)(tok0 + t) * 400 + u * 4);
        }
    };

    stage_x(blockIdx.x, xbb[0]);
    cp_commit();

    int p = 0;
    #pragma unroll 1
    for (int b = blockIdx.x; b < 800; b += 148) {
        const int nb = b + 148;
        if (nb < 800) { stage_x(nb, xbb[p ^ 1]); cp_commit(); cp_wait<1>(); }
        else          { cp_wait<0>(); }
        __syncthreads();

        const float* xb = xbf[p];
        u64 acc[4];
        #pragma unroll
        for (int i = 0; i < 4; i++) acc[i] = 0ull;

        #pragma unroll 1
        for (int s = 0; s < 12; s++) {
            #pragma unroll
            for (int q = 0; q < 8; q++) {
                const ulonglong2 w = *reinterpret_cast<const ulonglong2*>(
                    sw + ((s * 64 + c) * 8 + (q ^ (c & 7))) * 4);
                #pragma unroll
                for (int i = 0; i < 4; i++) {
                    const ulonglong2 xv = *reinterpret_cast<const ulonglong2*>(
                        xb + ((slot * 4 + i) * PJ_XU + s * 8 + q) * 4);
                    ffma2(acc[i], xv.x, w.x);
                    ffma2(acc[i], xv.y, w.y);
                }
            }
        }
        #pragma unroll
        for (int q = 0; q < 4; q++) {      // seg 12: k = 384..399
            const ulonglong2 w = *reinterpret_cast<const ulonglong2*>(
                sw + ((12 * 64 + c) * 8 + (q ^ (c & 7))) * 4);
            #pragma unroll
            for (int i = 0; i < 4; i++) {
                const ulonglong2 xv = *reinterpret_cast<const ulonglong2*>(
                    xb + ((slot * 4 + i) * PJ_XU + 96 + q) * 4);
                ffma2(acc[i], xv.x, w.x);
                ffma2(acc[i], xv.y, w.y);
            }
        }

        const int tok0 = b * 32;
        #pragma unroll
        for (int i = 0; i < 4; i++)
            xout[(size_t)(tok0 + slot * 4 + i) * 128 + h * 64 + c] = hadd2(acc[i]);

        __syncthreads();                  // panel p free for restage
        p ^= 1;
    }
}

// ---------------------------------------------------------------------------
// Kernel C2: one highway layer. grid 148, 512 threads, 1 CTA/SM.
// tw+gw staged ONCE into XOR-swizzled atoms (atom row = s*128 + c).
// 64-token batches double-buffered; thread = (c2 = tid&63 -> ch c2,c2+64;
// tq = tid>>6 -> 8 tokens).  x' = sig(g)*relu(t) + (1-sig(g))*x.
// ---------------------------------------------------------------------------
#define HW_WF   (2 * 512 * 32)             // 32768 floats (131072 B)
#define HW_XU   33                         // float4 units per token row
#define HW_XF   (64 * HW_XU * 4)           // 8448 floats per buffer
#define HW_SMEM ((HW_WF + 2 * HW_XF) * 4)  // 198656 B

__global__ void __launch_bounds__(512, 1)
hwy_kernel(const float* __restrict__ tw, const float* __restrict__ tb,
           const float* __restrict__ gw, const float* __restrict__ gb,
           const float* __restrict__ xin, float* __restrict__ xout)
{
    extern __shared__ float sm[];
    float* sw  = sm;                       // [2 mats][512 atoms][32 floats]
    float* xb0 = sw + HW_WF;
    float* xb1 = xb0 + HW_XF;
    const uint32_t swb  = smem_u32(sw);
    const uint32_t xbb[2] = { smem_u32(xb0), smem_u32(xb1) };
    float* const xbf[2] = { xb0, xb1 };

    const int tid = threadIdx.x;
    const int c2  = tid & 63;
    const int tq  = tid >> 6;

    const float tb0v = __ldg(tb + c2), tb1v = __ldg(tb + c2 + 64);
    const float gb0v = __ldg(gb + c2), gb1v = __ldg(gb + c2 + 64);

    // ---- stage both weight matrices once ---------------------------------
    #pragma unroll 1
    for (int i = tid; i < 8192; i += 512) {
        const int m = i >> 12;
        const int r = (i >> 3) & 511;      // atom row = s*128 + c
        const int q = i & 7;
        const int cc = r & 127;
        const int dst = m * 4096 + r * 8 + (q ^ (cc & 7));
        const float* src = (m ? gw : tw) + cc * 128 + (r >> 7) * 32 + q * 4;
        cp16(swb + (uint32_t)dst * 16u, src);
    }
    cp_commit();

    auto stage_x = [&](int b, uint32_t xb) {
        const int tok0 = b * 64;
        #pragma unroll 1
        for (int i = tid; i < 2048; i += 512) {
            const int t = i >> 5, u = i & 31;
            cp16(xb + (uint32_t)(t * HW_XU + u) * 16u,
                 xin + (size_t)(tok0 + t) * 128 + u * 4);
        }
    };

    stage_x(blockIdx.x, xbb[0]);
    cp_commit();

    int p = 0;
    #pragma unroll 1
    for (int b = blockIdx.x; b < 400; b += 148) {
        const int nb = b + 148;
        if (nb < 400) { stage_x(nb, xbb[p ^ 1]); cp_commit(); cp_wait<1>(); }
        else          { cp_wait<0>(); }
        __syncthreads();

        const float* xb = xbf[p];
        u64 at0[8], at1[8], ag0[8], ag1[8];
        #pragma unroll
        for (int i = 0; i < 8; i++) { at0[i] = at1[i] = ag0[i] = ag1[i] = 0ull; }

        #pragma unroll 1
        for (int s = 0; s < 4; s++) {
            #pragma unroll
            for (int q = 0; q < 8; q++) {
                const int qq0 = q ^ (c2 & 7);
                const ulonglong2 wt0 = *reinterpret_cast<const ulonglong2*>(
                    sw + ((s * 128 + c2) * 8 + qq0) * 4);
                const ulonglong2 wt1 = *reinterpret_cast<const ulonglong2*>(
                    sw + ((s * 128 + c2 + 64) * 8 + qq0) * 4);
                const ulonglong2 wg0 = *reinterpret_cast<const ulonglong2*>(
                    sw + 16384 + ((s * 128 + c2) * 8 + qq0) * 4);
                const ulonglong2 wg1 = *reinterpret_cast<const ulonglong2*>(
                    sw + 16384 + ((s * 128 + c2 + 64) * 8 + qq0) * 4);
                #pragma unroll
                for (int i = 0; i < 8; i++) {
                    const ulonglong2 xv = *reinterpret_cast<const ulonglong2*>(
                        xb + ((tq * 8 + i) * HW_XU + s * 8 + q) * 4);
                    ffma2(at0[i], xv.x, wt0.x); ffma2(at0[i], xv.y, wt0.y);
                    ffma2(at1[i], xv.x, wt1.x); ffma2(at1[i], xv.y, wt1.y);
                    ffma2(ag0[i], xv.x, wg0.x); ffma2(ag0[i], xv.y, wg0.y);
                    ffma2(ag1[i], xv.x, wg1.x); ffma2(ag1[i], xv.y, wg1.y);
                }
            }
        }

        const int tok0 = b * 64;
        #pragma unroll
        for (int i = 0; i < 8; i++) {
            const int t = tq * 8 + i;
            const float xo0 = xb[t * (HW_XU * 4) + c2];
            const float xo1 = xb[t * (HW_XU * 4) + c2 + 64];
            const float tv0 = fmaxf(hadd2(at0[i]) + tb0v, 0.0f);
            const float tv1 = fmaxf(hadd2(at1[i]) + tb1v, 0.0f);
            const float g0  = 0.5f * tanh_fast(0.5f * (hadd2(ag0[i]) + gb0v)) + 0.5f;
            const float g1  = 0.5f * tanh_fast(0.5f * (hadd2(ag1[i]) + gb1v)) + 0.5f;
            xout[(size_t)(tok0 + t) * 128 + c2]      = g0 * tv0 + (1.0f - g0) * xo0;
            xout[(size_t)(tok0 + t) * 128 + c2 + 64] = g1 * tv1 + (1.0f - g1) * xo1;
        }

        __syncthreads();                  // panel p free for restage
        p ^= 1;
    }
}

// ---------------------------------------------------------------------------
extern "C" void kernel_launch(void* const* d_in, const int* in_sizes, int n_in,
                              void* d_out, int out_size)
{
    const int*   idxs = (const int*)  d_in[0];
    const float* cv   = (const float*)d_in[1];
    const float* f2   = (const float*)d_in[2];
    const float* f3   = (const float*)d_in[3];
    const float* f4   = (const float*)d_in[4];
    const float* f5   = (const float*)d_in[5];
    const float* wp   = (const float*)d_in[6];
    const float* tw0  = (const float*)d_in[7];
    const float* tb0  = (const float*)d_in[8];
    const float* tw1  = (const float*)d_in[9];
    const float* tb1  = (const float*)d_in[10];
    const float* gw0  = (const float*)d_in[11];
    const float* gb0  = (const float*)d_in[12];
    const float* gw1  = (const float*)d_in[13];
    const float* gb1  = (const float*)d_in[14];
    float* out = (float*)d_out;

    static bool attr_done = false;
    if (!attr_done) {
        cudaFuncSetAttribute(conv_sum_kernel,
                             cudaFuncAttributeMaxDynamicSharedMemorySize, SMEMB_BYTES);
        cudaFuncSetAttribute(proj_kernel,
                             cudaFuncAttributeMaxDynamicSharedMemorySize, PJ_SMEM);
        cudaFuncSetAttribute(hwy_kernel,
                             cudaFuncAttributeMaxDynamicSharedMemorySize, HW_SMEM);
        attr_done = true;
    }

    float* x1; cudaGetSymbolAddress((void**)&x1, g_x1);
    float* x2; cudaGetSymbolAddress((void**)&x2, g_x2);

    pp_kernel<<<dim3(96, 14), 128>>>(cv, f2, f3, f4, f5);
    conv_sum_kernel<<<NTOK / 64, TB1, SMEMB_BYTES>>>(idxs);
    proj_kernel<<<dim3(148, 2), 512, PJ_SMEM>>>(wp, x1);
    hwy_kernel<<<148, 512, HW_SMEM>>>(tw0, tb0, gw0, gb0, x1, x2);
    hwy_kernel<<<148, 512, HW_SMEM>>>(tw1, tb1, gw1, gb1, x2, out);
}

// round 11
// speedup vs baseline: 1.2784x; 1.2784x over previous
#include <cuda_runtime.h>
#include <cstdint>

// ---------------------------------------------------------------------------
// CharacterEmbeddingLayer via vocabulary factorization + split head.
//  - conv: PP[char][piece][filter] precompute; conv = table adds + max;
//    tanh outside max (monotonic).  (exact R5 config, measured best)
//  - proj: x-panel resident per CTA (64 tokens), weights streamed in
//    double-buffered chunks (ratio-1.0 inner loop, 8 tokens per weight load).
//  - hwy: resident weights, 64-token streamed batches (exact R10, 53 us).
// ---------------------------------------------------------------------------

#define NTOK  25600      // 64*400 tokens

typedef unsigned long long u64;

// PP table: [13 filter-chunks][96 chars][14 pieces][8 filters]
__device__ float g_pp[13 * 96 * 14 * 8];
// conv outputs: [NTOK][400]
__device__ float g_outs[(size_t)NTOK * 400];
// head intermediates: [NTOK][128]
__device__ float g_x1[(size_t)NTOK * 128];
__device__ float g_x2[(size_t)NTOK * 128];

// ---------------- packed fp32x2 + async helpers -----------------------------
__device__ __forceinline__ void ffma2(u64 &acc, u64 a, u64 b) {
    asm("fma.rn.f32x2 %0, %1, %2, %0;" : "+l"(acc) : "l"(a), "l"(b));
}
__device__ __forceinline__ u64 fadd2(u64 a, u64 b) {
    u64 r; asm("add.rn.f32x2 %0, %1, %2;" : "=l"(r) : "l"(a), "l"(b)); return r;
}
__device__ __forceinline__ void unpack2(u64 v, float &lo, float &hi) {
    asm("mov.b64 {%0, %1}, %2;" : "=f"(lo), "=f"(hi) : "l"(v));
}
__device__ __forceinline__ float hadd2(u64 v) {
    float lo, hi; unpack2(v, lo, hi); return lo + hi;
}
__device__ __forceinline__ float tanh_fast(float x) {
    float y;
    asm("tanh.approx.f32 %0, %1;" : "=f"(y) : "f"(x));
    return y;
}
__device__ __forceinline__ uint32_t smem_u32(const void* p) {
    return (uint32_t)__cvta_generic_to_shared(p);
}
__device__ __forceinline__ void cp16(uint32_t dst, const void* src) {
    asm volatile("cp.async.ca.shared.global [%0], [%1], 16;" :: "r"(dst), "l"(src));
}
__device__ __forceinline__ void cp8(uint32_t dst, const void* src) {
    asm volatile("cp.async.ca.shared.global [%0], [%1], 8;" :: "r"(dst), "l"(src));
}
__device__ __forceinline__ void cp_commit() {
    asm volatile("cp.async.commit_group;");
}
template<int N> __device__ __forceinline__ void cp_wait() {
    asm volatile("cp.async.wait_group %0;" :: "n"(N));
}

// ---------------------------------------------------------------------------
// Kernel A: precompute PP.  grid = (96 chars, 14 pieces), 128 threads.
// ---------------------------------------------------------------------------
__global__ void pp_kernel(const float* __restrict__ cv,
                          const float* __restrict__ f2, const float* __restrict__ f3,
                          const float* __restrict__ f4, const float* __restrict__ f5)
{
    __shared__ float scv[64];
    const int c  = blockIdx.x;
    const int pg = blockIdx.y;
    const int j  = threadIdx.x;
    if (j < 64) scv[j] = __ldg(cv + c * 64 + j);
    __syncthreads();

    if (j < 104) {
        float s = 0.0f;
        if (j < 100) {
            const float* fp; int pl, RL;
            if (pg < 2)      { fp = f2; pl = pg;     RL = 2; }
            else if (pg < 5) { fp = f3; pl = pg - 2; RL = 3; }
            else if (pg < 9) { fp = f4; pl = pg - 5; RL = 4; }
            else             { fp = f5; pl = pg - 9; RL = 5; }
            const float4* fr = reinterpret_cast<const float4*>(fp + (j * RL + pl) * 64);
            #pragma unroll 4
            for (int q = 0; q < 16; q++) {
                const float4 fv = __ldg(fr + q);
                s += scv[4*q]   * fv.x + scv[4*q+1] * fv.y
                   + scv[4*q+2] * fv.z + scv[4*q+3] * fv.w;
            }
        }
        g_pp[(((j >> 3) * 96 + c) * 14 + pg) * 8 + (j & 7)] = s;
    }
}

// ---------------------------------------------------------------------------
// Kernel B: conv as table sums (exact R5 config).  grid = 400 (64 tok/CTA),
// 256 threads, 2 CTAs/SM. thread = (token t = tid>>2, filter-pair j2).
// ---------------------------------------------------------------------------
#define TB1  256
#define CHUNK_U64 (96 * 14 * 5)            // 6720 u64 per buffer
#define SMEMB_BYTES (2 * CHUNK_U64 * 8)    // 107520 B

__device__ __forceinline__ void stage_chunk(uint32_t sbuf,
                                            const float* __restrict__ src, int tid)
{
    #pragma unroll 1
    for (int i = tid; i < 5376; i += TB1) {       // 1344 rows x 4 u64
        const int r = i >> 2, e = i & 3;
        cp8(sbuf + (uint32_t)(r * 5 + e) * 8u, src + 2 * i);
    }
}

template<int W, int PB, int BOFF>
__device__ __forceinline__ void branch_sum(const u64* __restrict__ s_pp,
                                           const int (&bix)[16],
                                           float* __restrict__ orow,
                                           int g, int j2)
{
    constexpr int L = 17 - W;
    float m0 = -1e30f, m1 = -1e30f;
    #pragma unroll
    for (int l = 0; l < L; l++) {
        u64 a = s_pp[bix[l] + PB * 5];
        #pragma unroll
        for (int p = 1; p < W; p++)
            a = fadd2(a, s_pp[bix[l + p] + (PB + p) * 5]);
        float lo, hi; unpack2(a, lo, hi);
        m0 = fmaxf(m0, lo);
        m1 = fmaxf(m1, hi);
    }
    if (g < 12 || j2 < 2) {     // chunk 12: only filters 96..99 are real
        float2 r;
        r.x = tanh_fast(m0);
        r.y = tanh_fast(m1);
        *reinterpret_cast<float2*>(orow + BOFF + g * 8 + j2 * 2) = r;
    }
}

__global__ void __launch_bounds__(TB1, 2)
conv_sum_kernel(const int* __restrict__ idxs)
{
    extern __shared__ u64 s_pp2[];
    u64* buf0 = s_pp2;
    u64* buf1 = s_pp2 + CHUNK_U64;
    const uint32_t sb0 = smem_u32(buf0);
    const uint32_t sb1 = smem_u32(buf1);

    const int tid = threadIdx.x;
    const int j2  = tid & 3;
    const int token = blockIdx.x * 64 + (tid >> 2);

    int bix[16];
    {
        const int4* ip4 = reinterpret_cast<const int4*>(idxs + token * 16);
        const int4 A = __ldg(ip4 + 0), B = __ldg(ip4 + 1);
        const int4 C = __ldg(ip4 + 2), D = __ldg(ip4 + 3);
        bix[ 0] = A.x * 70 + j2; bix[ 1] = A.y * 70 + j2;
        bix[ 2] = A.z * 70 + j2; bix[ 3] = A.w * 70 + j2;
        bix[ 4] = B.x * 70 + j2; bix[ 5] = B.y * 70 + j2;
        bix[ 6] = B.z * 70 + j2; bix[ 7] = B.w * 70 + j2;
        bix[ 8] = C.x * 70 + j2; bix[ 9] = C.y * 70 + j2;
        bix[10] = C.z * 70 + j2; bix[11] = C.w * 70 + j2;
        bix[12] = D.x * 70 + j2; bix[13] = D.y * 70 + j2;
        bix[14] = D.z * 70 + j2; bix[15] = D.w * 70 + j2;
    }

    float* orow = g_outs + (size_t)token * 400;

    stage_chunk(sb0, g_pp, tid);
    cp_commit();

    #pragma unroll 1
    for (int g = 0; g < 13; g++) {
        if (g < 12) {
            stage_chunk((g & 1) ? sb0 : sb1, g_pp + (g + 1) * 10752, tid);
            cp_commit();
            cp_wait<1>();
        } else {
            cp_wait<0>();
        }
        __syncthreads();
        const u64* sp = (g & 1) ? buf1 : buf0;
        branch_sum<2, 0,   0>(sp, bix, orow, g, j2);
        branch_sum<3, 2, 100>(sp, bix, orow, g, j2);
        branch_sum<4, 5, 200>(sp, bix, orow, g, j2);
        branch_sum<5, 9, 300>(sp, bix, orow, g, j2);
        __syncthreads();                  // buffer g&1 free for restage
    }
}

// ---------------------------------------------------------------------------
// Kernel C1: projection, x-resident / weight-streamed.  grid 400 (64 tok/CTA),
// 512 threads, 1 CTA/SM.  x panel (64 x 404 floats, 103KB) staged ONCE;
// w_proj streamed in 10 double-buffered chunks of [128][40] (pitch 44 ->
// (r*11+u) mod 8 distinct -> conflict-free LDS.128).
// thread = (c2 = tid&63 -> channels c2,c2+64; tq = tid>>6 -> 8 tokens):
// per k4 step 2 weight loads serve 16 token-accs -> crossbar:fma = 1.0.
// ---------------------------------------------------------------------------
#define PJ_XROW 404                        // floats per token row (101 float4)
#define PJ_XF   (64 * PJ_XROW)             // 25856 floats
#define PJ_WP   44                         // chunk row pitch (floats)
#define PJ_WF   (128 * PJ_WP)              // 5632 floats per buffer
#define PJ_SMEM ((PJ_XF + 2 * PJ_WF) * 4)  // 148480 B

__global__ void __launch_bounds__(512, 1)
proj_kernel(const float* __restrict__ wp, float* __restrict__ xout)
{
    extern __shared__ float sm[];
    float* s_x = sm;                       // [64][404]
    float* w0  = s_x + PJ_XF;              // [128][44]
    float* w1  = w0 + PJ_WF;
    const uint32_t xb  = smem_u32(s_x);
    const uint32_t wb[2] = { smem_u32(w0), smem_u32(w1) };
    float* const wf[2] = { w0, w1 };

    const int tid  = threadIdx.x;
    const int c2   = tid & 63;             // channels c2 and c2+64
    const int tq   = tid >> 6;             // token group 0..7
    const int tok0 = blockIdx.x * 64;

    // ---- stage x panel once ----------------------------------------------
    #pragma unroll 1
    for (int i = tid; i < 6400; i += 512) {        // 64 tokens x 100 quads
        const int t = i / 100, u = i - t * 100;
        cp16(xb + (uint32_t)(t * PJ_XROW + 4 * u) * 4u,
             g_outs + (size_t)(tok0 + t) * 400 + 4 * u);
    }
    cp_commit();

    auto stage_w = [&](int kc, uint32_t b) {
        #pragma unroll 1
        for (int i = tid; i < 1280; i += 512) {    // 128 rows x 10 quads
            const int r = i / 10, q = i - r * 10;
            cp16(b + (uint32_t)(r * PJ_WP + 4 * q) * 4u,
                 wp + r * 400 + kc * 40 + 4 * q);
        }
    };

    stage_w(0, wb[0]);
    cp_commit();

    u64 a0[8], a1[8];
    #pragma unroll
    for (int i = 0; i < 8; i++) { a0[i] = 0ull; a1[i] = 0ull; }

    #pragma unroll 1
    for (int kc = 0; kc < 10; kc++) {
        if (kc < 9) { stage_w(kc + 1, wb[(kc + 1) & 1]); cp_commit(); cp_wait<1>(); }
        else        { cp_wait<0>(); }
        __syncthreads();
        const float* b = wf[kc & 1];
        #pragma unroll
        for (int q = 0; q < 10; q++) {
            const ulonglong2 wa = *reinterpret_cast<const ulonglong2*>(b + c2 * PJ_WP + 4 * q);
            const ulonglong2 wv = *reinterpret_cast<const ulonglong2*>(b + (c2 + 64) * PJ_WP + 4 * q);
            #pragma unroll
            for (int i = 0; i < 8; i++) {
                const ulonglong2 xv = *reinterpret_cast<const ulonglong2*>(
                    s_x + (tq * 8 + i) * PJ_XROW + kc * 40 + 4 * q);
                ffma2(a0[i], xv.x, wa.x); ffma2(a0[i], xv.y, wa.y);
                ffma2(a1[i], xv.x, wv.x); ffma2(a1[i], xv.y, wv.y);
            }
        }
        __syncthreads();                  // weight buffer kc&1 free
    }

    #pragma unroll
    for (int i = 0; i < 8; i++) {
        const int t = tok0 + tq * 8 + i;
        xout[(size_t)t * 128 + c2]      = hadd2(a0[i]);
        xout[(size_t)t * 128 + c2 + 64] = hadd2(a1[i]);
    }
}

// ---------------------------------------------------------------------------
// Kernel C2: one highway layer (exact R10, measured 53us). grid 148,
// 512 threads, 1 CTA/SM. tw+gw resident (XOR-swizzled atoms); 64-token
// batches double-buffered.  x' = sig(g)*relu(t) + (1-sig(g))*x.
// ---------------------------------------------------------------------------
#define HW_WF   (2 * 512 * 32)             // 32768 floats (131072 B)
#define HW_XU   33                         // float4 units per token row
#define HW_XF   (64 * HW_XU * 4)           // 8448 floats per buffer
#define HW_SMEM ((HW_WF + 2 * HW_XF) * 4)  // 198656 B

__global__ void __launch_bounds__(512, 1)
hwy_kernel(const float* __restrict__ tw, const float* __restrict__ tb,
           const float* __restrict__ gw, const float* __restrict__ gb,
           const float* __restrict__ xin, float* __restrict__ xout)
{
    extern __shared__ float sm[];
    float* sw  = sm;                       // [2 mats][512 atoms][32 floats]
    float* xb0 = sw + HW_WF;
    float* xb1 = xb0 + HW_XF;
    const uint32_t swb  = smem_u32(sw);
    const uint32_t xbb[2] = { smem_u32(xb0), smem_u32(xb1) };
    float* const xbf[2] = { xb0, xb1 };

    const int tid = threadIdx.x;
    const int c2  = tid & 63;
    const int tq  = tid >> 6;

    const float tb0v = __ldg(tb + c2), tb1v = __ldg(tb + c2 + 64);
    const float gb0v = __ldg(gb + c2), gb1v = __ldg(gb + c2 + 64);

    // ---- stage both weight matrices once ---------------------------------
    #pragma unroll 1
    for (int i = tid; i < 8192; i += 512) {
        const int m = i >> 12;
        const int r = (i >> 3) & 511;      // atom row = s*128 + c
        const int q = i & 7;
        const int cc = r & 127;
        const int dst = m * 4096 + r * 8 + (q ^ (cc & 7));
        const float* src = (m ? gw : tw) + cc * 128 + (r >> 7) * 32 + q * 4;
        cp16(swb + (uint32_t)dst * 16u, src);
    }
    cp_commit();

    auto stage_x = [&](int b, uint32_t xbuf) {
        const int tok0 = b * 64;
        #pragma unroll 1
        for (int i = tid; i < 2048; i += 512) {
            const int t = i >> 5, u = i & 31;
            cp16(xbuf + (uint32_t)(t * HW_XU + u) * 16u,
                 xin + (size_t)(tok0 + t) * 128 + u * 4);
        }
    };

    stage_x(blockIdx.x, xbb[0]);
    cp_commit();

    int p = 0;
    #pragma unroll 1
    for (int b = blockIdx.x; b < 400; b += 148) {
        const int nb = b + 148;
        if (nb < 400) { stage_x(nb, xbb[p ^ 1]); cp_commit(); cp_wait<1>(); }
        else          { cp_wait<0>(); }
        __syncthreads();

        const float* xb = xbf[p];
        u64 at0[8], at1[8], ag0[8], ag1[8];
        #pragma unroll
        for (int i = 0; i < 8; i++) { at0[i] = at1[i] = ag0[i] = ag1[i] = 0ull; }

        #pragma unroll 1
        for (int s = 0; s < 4; s++) {
            #pragma unroll
            for (int q = 0; q < 8; q++) {
                const int qq0 = q ^ (c2 & 7);
                const ulonglong2 wt0 = *reinterpret_cast<const ulonglong2*>(
                    sw + ((s * 128 + c2) * 8 + qq0) * 4);
                const ulonglong2 wt1 = *reinterpret_cast<const ulonglong2*>(
                    sw + ((s * 128 + c2 + 64) * 8 + qq0) * 4);
                const ulonglong2 wg0 = *reinterpret_cast<const ulonglong2*>(
                    sw + 16384 + ((s * 128 + c2) * 8 + qq0) * 4);
                const ulonglong2 wg1 = *reinterpret_cast<const ulonglong2*>(
                    sw + 16384 + ((s * 128 + c2 + 64) * 8 + qq0) * 4);
                #pragma unroll
                for (int i = 0; i < 8; i++) {
                    const ulonglong2 xv = *reinterpret_cast<const ulonglong2*>(
                        xb + ((tq * 8 + i) * HW_XU + s * 8 + q) * 4);
                    ffma2(at0[i], xv.x, wt0.x); ffma2(at0[i], xv.y, wt0.y);
                    ffma2(at1[i], xv.x, wt1.x); ffma2(at1[i], xv.y, wt1.y);
                    ffma2(ag0[i], xv.x, wg0.x); ffma2(ag0[i], xv.y, wg0.y);
                    ffma2(ag1[i], xv.x, wg1.x); ffma2(ag1[i], xv.y, wg1.y);
                }
            }
        }

        const int tok0 = b * 64;
        #pragma unroll
        for (int i = 0; i < 8; i++) {
            const int t = tq * 8 + i;
            const float xo0 = xb[t * (HW_XU * 4) + c2];
            const float xo1 = xb[t * (HW_XU * 4) + c2 + 64];
            const float tv0 = fmaxf(hadd2(at0[i]) + tb0v, 0.0f);
            const float tv1 = fmaxf(hadd2(at1[i]) + tb1v, 0.0f);
            const float g0  = 0.5f * tanh_fast(0.5f * (hadd2(ag0[i]) + gb0v)) + 0.5f;
            const float g1  = 0.5f * tanh_fast(0.5f * (hadd2(ag1[i]) + gb1v)) + 0.5f;
            xout[(size_t)(tok0 + t) * 128 + c2]      = g0 * tv0 + (1.0f - g0) * xo0;
            xout[(size_t)(tok0 + t) * 128 + c2 + 64] = g1 * tv1 + (1.0f - g1) * xo1;
        }

        __syncthreads();                  // panel p free for restage
        p ^= 1;
    }
}

// ---------------------------------------------------------------------------
extern "C" void kernel_launch(void* const* d_in, const int* in_sizes, int n_in,
                              void* d_out, int out_size)
{
    const int*   idxs = (const int*)  d_in[0];
    const float* cv   = (const float*)d_in[1];
    const float* f2   = (const float*)d_in[2];
    const float* f3   = (const float*)d_in[3];
    const float* f4   = (const float*)d_in[4];
    const float* f5   = (const float*)d_in[5];
    const float* wp   = (const float*)d_in[6];
    const float* tw0  = (const float*)d_in[7];
    const float* tb0  = (const float*)d_in[8];
    const float* tw1  = (const float*)d_in[9];
    const float* tb1  = (const float*)d_in[10];
    const float* gw0  = (const float*)d_in[11];
    const float* gb0  = (const float*)d_in[12];
    const float* gw1  = (const float*)d_in[13];
    const float* gb1  = (const float*)d_in[14];
    float* out = (float*)d_out;

    static bool attr_done = false;
    if (!attr_done) {
        cudaFuncSetAttribute(conv_sum_kernel,
                             cudaFuncAttributeMaxDynamicSharedMemorySize, SMEMB_BYTES);
        cudaFuncSetAttribute(proj_kernel,
                             cudaFuncAttributeMaxDynamicSharedMemorySize, PJ_SMEM);
        cudaFuncSetAttribute(hwy_kernel,
                             cudaFuncAttributeMaxDynamicSharedMemorySize, HW_SMEM);
        attr_done = true;
    }

    float* x1; cudaGetSymbolAddress((void**)&x1, g_x1);
    float* x2; cudaGetSymbolAddress((void**)&x2, g_x2);

    pp_kernel<<<dim3(96, 14), 128>>>(cv, f2, f3, f4, f5);
    conv_sum_kernel<<<NTOK / 64, TB1, SMEMB_BYTES>>>(idxs);
    proj_kernel<<<NTOK / 64, 512, PJ_SMEM>>>(wp, x1);
    hwy_kernel<<<148, 512, HW_SMEM>>>(tw0, tb0, gw0, gb0, x1, x2);
    hwy_kernel<<<148, 512, HW_SMEM>>>(tw1, tb1, gw1, gb1, x2, out);
}

// round 12
// speedup vs baseline: 1.3692x; 1.0710x over previous
#include <cuda_runtime.h>
#include <cstdint>

// ---------------------------------------------------------------------------
// CharacterEmbeddingLayer via vocabulary factorization + split head.
//  - conv: PP table (padded rows baked into g_pp) bulk-copied per chunk with
//    cp.async.bulk + mbarrier  -> no per-element LDGSTS issue cost.
//  - proj: x-panel resident (bulk-copied), weights streamed (cp16 chunks).
//  - hwy: resident weights, streamed 64-token batches (measured 53us).
// ---------------------------------------------------------------------------

#define NTOK  25600      // 64*400 tokens

typedef unsigned long long u64;

// PP table WITH padding baked in: [13 chunks][96 chars][14 pieces][10 floats]
// (floats 0..7 = filter values, 8..9 = pad).  One chunk = 53760 B contiguous.
__device__ __align__(128) float g_pp[13 * 96 * 14 * 10];
// conv outputs: [NTOK][400]
__device__ __align__(128) float g_outs[(size_t)NTOK * 400];
// head intermediates: [NTOK][128]
__device__ __align__(128) float g_x1[(size_t)NTOK * 128];
__device__ __align__(128) float g_x2[(size_t)NTOK * 128];

// ---------------- packed fp32x2 + async helpers -----------------------------
__device__ __forceinline__ void ffma2(u64 &acc, u64 a, u64 b) {
    asm("fma.rn.f32x2 %0, %1, %2, %0;" : "+l"(acc) : "l"(a), "l"(b));
}
__device__ __forceinline__ u64 fadd2(u64 a, u64 b) {
    u64 r; asm("add.rn.f32x2 %0, %1, %2;" : "=l"(r) : "l"(a), "l"(b)); return r;
}
__device__ __forceinline__ void unpack2(u64 v, float &lo, float &hi) {
    asm("mov.b64 {%0, %1}, %2;" : "=f"(lo), "=f"(hi) : "l"(v));
}
__device__ __forceinline__ float hadd2(u64 v) {
    float lo, hi; unpack2(v, lo, hi); return lo + hi;
}
__device__ __forceinline__ float tanh_fast(float x) {
    float y;
    asm("tanh.approx.f32 %0, %1;" : "=f"(y) : "f"(x));
    return y;
}
__device__ __forceinline__ uint32_t smem_u32(const void* p) {
    return (uint32_t)__cvta_generic_to_shared(p);
}
__device__ __forceinline__ void cp16(uint32_t dst, const void* src) {
    asm volatile("cp.async.ca.shared.global [%0], [%1], 16;" :: "r"(dst), "l"(src));
}
__device__ __forceinline__ void cp_commit() {
    asm volatile("cp.async.commit_group;");
}
template<int N> __device__ __forceinline__ void cp_wait() {
    asm volatile("cp.async.wait_group %0;" :: "n"(N));
}
// ---- bulk-copy (UBLKCP) + mbarrier ----------------------------------------
__device__ __forceinline__ void mbar_init(uint32_t mbar, uint32_t cnt) {
    asm volatile("mbarrier.init.shared.b64 [%0], %1;" :: "r"(mbar), "r"(cnt) : "memory");
}
__device__ __forceinline__ void mbar_expect(uint32_t mbar, uint32_t tx) {
    asm volatile("mbarrier.arrive.expect_tx.shared.b64 _, [%0], %1;"
                 :: "r"(mbar), "r"(tx) : "memory");
}
__device__ __forceinline__ void bulk_g2s(uint32_t dst, const void* src,
                                         uint32_t bytes, uint32_t mbar) {
    asm volatile(
        "cp.async.bulk.shared::cluster.global.mbarrier::complete_tx::bytes "
        "[%0], [%1], %2, [%3];"
        :: "r"(dst), "l"(src), "r"(bytes), "r"(mbar) : "memory");
}
__device__ __forceinline__ void mbar_wait(uint32_t mbar, uint32_t parity) {
    asm volatile(
        "{\n\t.reg .pred P;\n"
        "WL_%=:\n\t"
        "mbarrier.try_wait.parity.acquire.cta.shared::cta.b64 P, [%0], %1, 0x989680;\n\t"
        "@P bra.uni WD_%=;\n\t"
        "bra.uni WL_%=;\n\t"
        "WD_%=:\n\t}"
        :: "r"(mbar), "r"(parity) : "memory");
}

// ---------------------------------------------------------------------------
// Kernel A: precompute PP (padded layout).  grid = (96, 14), 128 threads.
// ---------------------------------------------------------------------------
__global__ void pp_kernel(const float* __restrict__ cv,
                          const float* __restrict__ f2, const float* __restrict__ f3,
                          const float* __restrict__ f4, const float* __restrict__ f5)
{
    __shared__ float scv[64];
    const int c  = blockIdx.x;
    const int pg = blockIdx.y;
    const int j  = threadIdx.x;
    if (j < 64) scv[j] = __ldg(cv + c * 64 + j);
    __syncthreads();

    if (j < 104) {
        float s = 0.0f;
        if (j < 100) {
            const float* fp; int pl, RL;
            if (pg < 2)      { fp = f2; pl = pg;     RL = 2; }
            else if (pg < 5) { fp = f3; pl = pg - 2; RL = 3; }
            else if (pg < 9) { fp = f4; pl = pg - 5; RL = 4; }
            else             { fp = f5; pl = pg - 9; RL = 5; }
            const float4* fr = reinterpret_cast<const float4*>(fp + (j * RL + pl) * 64);
            #pragma unroll 4
            for (int q = 0; q < 16; q++) {
                const float4 fv = __ldg(fr + q);
                s += scv[4*q]   * fv.x + scv[4*q+1] * fv.y
                   + scv[4*q+2] * fv.z + scv[4*q+3] * fv.w;
            }
        }
        // padded layout: chunk g = j>>3, float slot = j&7 within 10-float row
        g_pp[(j >> 3) * 13440 + (c * 14 + pg) * 10 + (j & 7)] = s;
    }
}

// ---------------------------------------------------------------------------
// Kernel B: conv as table sums.  grid = 400 (64 tok/CTA), 256 threads,
// 2 CTAs/SM. thread = (token t = tid>>2, filter-pair j2).  Chunks bulk-copied
// (one UBLKCP each) into double-buffered smem; layout identical to before
// (5-u64 rows, char stride 70 u64) so the read path is unchanged.
// ---------------------------------------------------------------------------
#define TB1  256
#define CHUNK_U64   6720                   // 96*14*5
#define CHUNK_BYTES 53760
#define SMEMB_BYTES (2 * CHUNK_BYTES)      // 107520 B

template<int W, int PB, int BOFF>
__device__ __forceinline__ void branch_sum(const u64* __restrict__ s_pp,
                                           const int (&bix)[16],
                                           float* __restrict__ orow,
                                           int g, int j2)
{
    constexpr int L = 17 - W;
    float m0 = -1e30f, m1 = -1e30f;
    #pragma unroll
    for (int l = 0; l < L; l++) {
        u64 a = s_pp[bix[l] + PB * 5];
        #pragma unroll
        for (int p = 1; p < W; p++)
            a = fadd2(a, s_pp[bix[l + p] + (PB + p) * 5]);
        float lo, hi; unpack2(a, lo, hi);
        m0 = fmaxf(m0, lo);
        m1 = fmaxf(m1, hi);
    }
    if (g < 12 || j2 < 2) {     // chunk 12: only filters 96..99 are real
        float2 r;
        r.x = tanh_fast(m0);
        r.y = tanh_fast(m1);
        *reinterpret_cast<float2*>(orow + BOFF + g * 8 + j2 * 2) = r;
    }
}

__global__ void __launch_bounds__(TB1, 2)
conv_sum_kernel(const int* __restrict__ idxs)
{
    extern __shared__ u64 s_pp2[];
    __shared__ __align__(8) u64 mb[2];
    u64* buf[2] = { s_pp2, s_pp2 + CHUNK_U64 };
    const uint32_t sb[2] = { smem_u32(buf[0]), smem_u32(buf[1]) };
    const uint32_t mbu[2] = { smem_u32(&mb[0]), smem_u32(&mb[1]) };

    const int tid = threadIdx.x;
    const int j2  = tid & 3;
    const int token = blockIdx.x * 64 + (tid >> 2);

    int bix[16];
    {
        const int4* ip4 = reinterpret_cast<const int4*>(idxs + token * 16);
        const int4 A = __ldg(ip4 + 0), B = __ldg(ip4 + 1);
        const int4 C = __ldg(ip4 + 2), D = __ldg(ip4 + 3);
        bix[ 0] = A.x * 70 + j2; bix[ 1] = A.y * 70 + j2;
        bix[ 2] = A.z * 70 + j2; bix[ 3] = A.w * 70 + j2;
        bix[ 4] = B.x * 70 + j2; bix[ 5] = B.y * 70 + j2;
        bix[ 6] = B.z * 70 + j2; bix[ 7] = B.w * 70 + j2;
        bix[ 8] = C.x * 70 + j2; bix[ 9] = C.y * 70 + j2;
        bix[10] = C.z * 70 + j2; bix[11] = C.w * 70 + j2;
        bix[12] = D.x * 70 + j2; bix[13] = D.y * 70 + j2;
        bix[14] = D.z * 70 + j2; bix[15] = D.w * 70 + j2;
    }

    float* orow = g_outs + (size_t)token * 400;

    if (tid == 0) { mbar_init(mbu[0], 1); mbar_init(mbu[1], 1); }
    __syncthreads();

    if (tid == 0) {
        mbar_expect(mbu[0], CHUNK_BYTES);
        bulk_g2s(sb[0], g_pp, CHUNK_BYTES, mbu[0]);
    }

    int ph0 = 0, ph1 = 0;
    #pragma unroll 1
    for (int g = 0; g < 13; g++) {
        if (g < 12 && tid == 0) {          // buffer (g+1)&1 freed at end of g-1
            const int b = (g + 1) & 1;
            mbar_expect(mbu[b], CHUNK_BYTES);
            bulk_g2s(sb[b], g_pp + (g + 1) * 13440, CHUNK_BYTES, mbu[b]);
        }
        if (g & 1) { mbar_wait(mbu[1], ph1); ph1 ^= 1; }
        else       { mbar_wait(mbu[0], ph0); ph0 ^= 1; }

        const u64* sp = buf[g & 1];
        branch_sum<2, 0,   0>(sp, bix, orow, g, j2);
        branch_sum<3, 2, 100>(sp, bix, orow, g, j2);
        branch_sum<4, 5, 200>(sp, bix, orow, g, j2);
        branch_sum<5, 9, 300>(sp, bix, orow, g, j2);
        __syncthreads();                  // buffer g&1 free for re-issue
    }
}

// ---------------------------------------------------------------------------
// Kernel C1: projection, x-resident / weight-streamed.  grid 400 (64 tok/CTA),
// 512 threads, 1 CTA/SM.  x panel (64x400 floats, contiguous 102400B) bulk-
// copied ONCE; w_proj streamed in 10 double-buffered cp16 chunks [128][40]
// (pitch 44).  thread = (c2 -> channels c2,c2+64; tq -> 8 tokens).
// x reads are warp-broadcast -> no padding needed.
// ---------------------------------------------------------------------------
#define PJ_XROW 400
#define PJ_XF   (64 * PJ_XROW)             // 25600 floats
#define PJ_WP   44
#define PJ_WF   (128 * PJ_WP)              // 5632 floats per buffer
#define PJ_SMEM ((PJ_XF + 2 * PJ_WF) * 4)  // 147456 B

__global__ void __launch_bounds__(512, 1)
proj_kernel(const float* __restrict__ wp, float* __restrict__ xout)
{
    extern __shared__ float sm[];
    __shared__ __align__(8) u64 pmb;
    float* s_x = sm;                       // [64][400]
    float* w0  = s_x + PJ_XF;              // [128][44]
    float* w1  = w0 + PJ_WF;
    const uint32_t xb  = smem_u32(s_x);
    const uint32_t wb[2] = { smem_u32(w0), smem_u32(w1) };
    const uint32_t pmbu = smem_u32(&pmb);
    float* const wf[2] = { w0, w1 };

    const int tid  = threadIdx.x;
    const int c2   = tid & 63;             // channels c2 and c2+64
    const int tq   = tid >> 6;             // token group 0..7
    const int tok0 = blockIdx.x * 64;

    if (tid == 0) mbar_init(pmbu, 1);
    __syncthreads();
    if (tid == 0) {
        mbar_expect(pmbu, PJ_XF * 4);
        bulk_g2s(xb, g_outs + (size_t)tok0 * 400, PJ_XF * 4, pmbu);
    }

    auto stage_w = [&](int kc, uint32_t b) {
        #pragma unroll 1
        for (int i = tid; i < 1280; i += 512) {    // 128 rows x 10 quads
            const int r = i / 10, q = i - r * 10;
            cp16(b + (uint32_t)(r * PJ_WP + 4 * q) * 4u,
                 wp + r * 400 + kc * 40 + 4 * q);
        }
    };

    stage_w(0, wb[0]);
    cp_commit();

    u64 a0[8], a1[8];
    #pragma unroll
    for (int i = 0; i < 8; i++) { a0[i] = 0ull; a1[i] = 0ull; }

    mbar_wait(pmbu, 0);                    // x panel ready

    #pragma unroll 1
    for (int kc = 0; kc < 10; kc++) {
        if (kc < 9) { stage_w(kc + 1, wb[(kc + 1) & 1]); cp_commit(); cp_wait<1>(); }
        else        { cp_wait<0>(); }
        __syncthreads();
        const float* b = wf[kc & 1];
        #pragma unroll
        for (int q = 0; q < 10; q++) {
            const ulonglong2 wa = *reinterpret_cast<const ulonglong2*>(b + c2 * PJ_WP + 4 * q);
            const ulonglong2 wv = *reinterpret_cast<const ulonglong2*>(b + (c2 + 64) * PJ_WP + 4 * q);
            #pragma unroll
            for (int i = 0; i < 8; i++) {
                const ulonglong2 xv = *reinterpret_cast<const ulonglong2*>(
                    s_x + (tq * 8 + i) * PJ_XROW + kc * 40 + 4 * q);
                ffma2(a0[i], xv.x, wa.x); ffma2(a0[i], xv.y, wa.y);
                ffma2(a1[i], xv.x, wv.x); ffma2(a1[i], xv.y, wv.y);
            }
        }
        __syncthreads();                  // weight buffer kc&1 free
    }

    #pragma unroll
    for (int i = 0; i < 8; i++) {
        const int t = tok0 + tq * 8 + i;
        xout[(size_t)t * 128 + c2]      = hadd2(a0[i]);
        xout[(size_t)t * 128 + c2 + 64] = hadd2(a1[i]);
    }
}

// ---------------------------------------------------------------------------
// Kernel C2: one highway layer (exact R10/R11, measured 53us). grid 148,
// 512 threads, 1 CTA/SM. tw+gw resident (XOR-swizzled atoms); 64-token
// batches double-buffered.  x' = sig(g)*relu(t) + (1-sig(g))*x.
// ---------------------------------------------------------------------------
#define HW_WF   (2 * 512 * 32)             // 32768 floats (131072 B)
#define HW_XU   33                         // float4 units per token row
#define HW_XF   (64 * HW_XU * 4)           // 8448 floats per buffer
#define HW_SMEM ((HW_WF + 2 * HW_XF) * 4)  // 198656 B

__global__ void __launch_bounds__(512, 1)
hwy_kernel(const float* __restrict__ tw, const float* __restrict__ tb,
           const float* __restrict__ gw, const float* __restrict__ gb,
           const float* __restrict__ xin, float* __restrict__ xout)
{
    extern __shared__ float sm[];
    float* sw  = sm;                       // [2 mats][512 atoms][32 floats]
    float* xb0 = sw + HW_WF;
    float* xb1 = xb0 + HW_XF;
    const uint32_t swb  = smem_u32(sw);
    const uint32_t xbb[2] = { smem_u32(xb0), smem_u32(xb1) };
    float* const xbf[2] = { xb0, xb1 };

    const int tid = threadIdx.x;
    const int c2  = tid & 63;
    const int tq  = tid >> 6;

    const float tb0v = __ldg(tb + c2), tb1v = __ldg(tb + c2 + 64);
    const float gb0v = __ldg(gb + c2), gb1v = __ldg(gb + c2 + 64);

    // ---- stage both weight matrices once ---------------------------------
    #pragma unroll 1
    for (int i = tid; i < 8192; i += 512) {
        const int m = i >> 12;
        const int r = (i >> 3) & 511;      // atom row = s*128 + c
        const int q = i & 7;
        const int cc = r & 127;
        const int dst = m * 4096 + r * 8 + (q ^ (cc & 7));
        const float* src = (m ? gw : tw) + cc * 128 + (r >> 7) * 32 + q * 4;
        cp16(swb + (uint32_t)dst * 16u, src);
    }
    cp_commit();

    auto stage_x = [&](int b, uint32_t xbuf) {
        const int tok0 = b * 64;
        #pragma unroll 1
        for (int i = tid; i < 2048; i += 512) {
            const int t = i >> 5, u = i & 31;
            cp16(xbuf + (uint32_t)(t * HW_XU + u) * 16u,
                 xin + (size_t)(tok0 + t) * 128 + u * 4);
        }
    };

    stage_x(blockIdx.x, xbb[0]);
    cp_commit();

    int p = 0;
    #pragma unroll 1
    for (int b = blockIdx.x; b < 400; b += 148) {
        const int nb = b + 148;
        if (nb < 400) { stage_x(nb, xbb[p ^ 1]); cp_commit(); cp_wait<1>(); }
        else          { cp_wait<0>(); }
        __syncthreads();

        const float* xb = xbf[p];
        u64 at0[8], at1[8], ag0[8], ag1[8];
        #pragma unroll
        for (int i = 0; i < 8; i++) { at0[i] = at1[i] = ag0[i] = ag1[i] = 0ull; }

        #pragma unroll 1
        for (int s = 0; s < 4; s++) {
            #pragma unroll
            for (int q = 0; q < 8; q++) {
                const int qq0 = q ^ (c2 & 7);
                const ulonglong2 wt0 = *reinterpret_cast<const ulonglong2*>(
                    sw + ((s * 128 + c2) * 8 + qq0) * 4);
                const ulonglong2 wt1 = *reinterpret_cast<const ulonglong2*>(
                    sw + ((s * 128 + c2 + 64) * 8 + qq0) * 4);
                const ulonglong2 wg0 = *reinterpret_cast<const ulonglong2*>(
                    sw + 16384 + ((s * 128 + c2) * 8 + qq0) * 4);
                const ulonglong2 wg1 = *reinterpret_cast<const ulonglong2*>(
                    sw + 16384 + ((s * 128 + c2 + 64) * 8 + qq0) * 4);
                #pragma unroll
                for (int i = 0; i < 8; i++) {
                    const ulonglong2 xv = *reinterpret_cast<const ulonglong2*>(
                        xb + ((tq * 8 + i) * HW_XU + s * 8 + q) * 4);
                    ffma2(at0[i], xv.x, wt0.x); ffma2(at0[i], xv.y, wt0.y);
                    ffma2(at1[i], xv.x, wt1.x); ffma2(at1[i], xv.y, wt1.y);
                    ffma2(ag0[i], xv.x, wg0.x); ffma2(ag0[i], xv.y, wg0.y);
                    ffma2(ag1[i], xv.x, wg1.x); ffma2(ag1[i], xv.y, wg1.y);
                }
            }
        }

        const int tok0 = b * 64;
        #pragma unroll
        for (int i = 0; i < 8; i++) {
            const int t = tq * 8 + i;
            const float xo0 = xb[t * (HW_XU * 4) + c2];
            const float xo1 = xb[t * (HW_XU * 4) + c2 + 64];
            const float tv0 = fmaxf(hadd2(at0[i]) + tb0v, 0.0f);
            const float tv1 = fmaxf(hadd2(at1[i]) + tb1v, 0.0f);
            const float g0  = 0.5f * tanh_fast(0.5f * (hadd2(ag0[i]) + gb0v)) + 0.5f;
            const float g1  = 0.5f * tanh_fast(0.5f * (hadd2(ag1[i]) + gb1v)) + 0.5f;
            xout[(size_t)(tok0 + t) * 128 + c2]      = g0 * tv0 + (1.0f - g0) * xo0;
            xout[(size_t)(tok0 + t) * 128 + c2 + 64] = g1 * tv1 + (1.0f - g1) * xo1;
        }

        __syncthreads();                  // panel p free for restage
        p ^= 1;
    }
}

// ---------------------------------------------------------------------------
extern "C" void kernel_launch(void* const* d_in, const int* in_sizes, int n_in,
                              void* d_out, int out_size)
{
    const int*   idxs = (const int*)  d_in[0];
    const float* cv   = (const float*)d_in[1];
    const float* f2   = (const float*)d_in[2];
    const float* f3   = (const float*)d_in[3];
    const float* f4   = (const float*)d_in[4];
    const float* f5   = (const float*)d_in[5];
    const float* wp   = (const float*)d_in[6];
    const float* tw0  = (const float*)d_in[7];
    const float* tb0  = (const float*)d_in[8];
    const float* tw1  = (const float*)d_in[9];
    const float* tb1  = (const float*)d_in[10];
    const float* gw0  = (const float*)d_in[11];
    const float* gb0  = (const float*)d_in[12];
    const float* gw1  = (const float*)d_in[13];
    const float* gb1  = (const float*)d_in[14];
    float* out = (float*)d_out;

    static bool attr_done = false;
    if (!attr_done) {
        cudaFuncSetAttribute(conv_sum_kernel,
                             cudaFuncAttributeMaxDynamicSharedMemorySize, SMEMB_BYTES);
        cudaFuncSetAttribute(proj_kernel,
                             cudaFuncAttributeMaxDynamicSharedMemorySize, PJ_SMEM);
        cudaFuncSetAttribute(hwy_kernel,
                             cudaFuncAttributeMaxDynamicSharedMemorySize, HW_SMEM);
        attr_done = true;
    }

    float* x1; cudaGetSymbolAddress((void**)&x1, g_x1);
    float* x2; cudaGetSymbolAddress((void**)&x2, g_x2);

    pp_kernel<<<dim3(96, 14), 128>>>(cv, f2, f3, f4, f5);
    conv_sum_kernel<<<NTOK / 64, TB1, SMEMB_BYTES>>>(idxs);
    proj_kernel<<<NTOK / 64, 512, PJ_SMEM>>>(wp, x1);
    hwy_kernel<<<148, 512, HW_SMEM>>>(tw0, tb0, gw0, gb0, x1, x2);
    hwy_kernel<<<148, 512, HW_SMEM>>>(tw1, tb1, gw1, gb1, x2, out);
}

// round 13
// speedup vs baseline: 1.3702x; 1.0008x over previous
#include <cuda_runtime.h>
#include <cstdint>

// ---------------------------------------------------------------------------
// CharacterEmbeddingLayer via vocabulary factorization + split head.
//  - conv: PP table (padded rows baked into g_pp) bulk-copied per chunk with
//    cp.async.bulk + mbarrier  (R12, measured good).
//  - proj: x-panel resident (bulk-copied), weights streamed (R12).
//  - hwy: CHANNEL-SPLIT resident weights (65KB/CTA) -> 2 CTAs/SM, 32 warps;
//    single x-panel per batch, co-resident CTA hides staging.
// ---------------------------------------------------------------------------

#define NTOK  25600      // 64*400 tokens

typedef unsigned long long u64;

// PP table WITH padding baked in: [13 chunks][96 chars][14 pieces][10 floats]
__device__ __align__(128) float g_pp[13 * 96 * 14 * 10];
// conv outputs: [NTOK][400]
__device__ __align__(128) float g_outs[(size_t)NTOK * 400];
// head intermediates: [NTOK][128]
__device__ __align__(128) float g_x1[(size_t)NTOK * 128];
__device__ __align__(128) float g_x2[(size_t)NTOK * 128];

// ---------------- packed fp32x2 + async helpers -----------------------------
__device__ __forceinline__ void ffma2(u64 &acc, u64 a, u64 b) {
    asm("fma.rn.f32x2 %0, %1, %2, %0;" : "+l"(acc) : "l"(a), "l"(b));
}
__device__ __forceinline__ u64 fadd2(u64 a, u64 b) {
    u64 r; asm("add.rn.f32x2 %0, %1, %2;" : "=l"(r) : "l"(a), "l"(b)); return r;
}
__device__ __forceinline__ void unpack2(u64 v, float &lo, float &hi) {
    asm("mov.b64 {%0, %1}, %2;" : "=f"(lo), "=f"(hi) : "l"(v));
}
__device__ __forceinline__ float hadd2(u64 v) {
    float lo, hi; unpack2(v, lo, hi); return lo + hi;
}
__device__ __forceinline__ float tanh_fast(float x) {
    float y;
    asm("tanh.approx.f32 %0, %1;" : "=f"(y) : "f"(x));
    return y;
}
__device__ __forceinline__ uint32_t smem_u32(const void* p) {
    return (uint32_t)__cvta_generic_to_shared(p);
}
__device__ __forceinline__ void cp16(uint32_t dst, const void* src) {
    asm volatile("cp.async.ca.shared.global [%0], [%1], 16;" :: "r"(dst), "l"(src));
}
__device__ __forceinline__ void cp_commit() {
    asm volatile("cp.async.commit_group;");
}
template<int N> __device__ __forceinline__ void cp_wait() {
    asm volatile("cp.async.wait_group %0;" :: "n"(N));
}
// ---- bulk-copy (UBLKCP) + mbarrier ----------------------------------------
__device__ __forceinline__ void mbar_init(uint32_t mbar, uint32_t cnt) {
    asm volatile("mbarrier.init.shared.b64 [%0], %1;" :: "r"(mbar), "r"(cnt) : "memory");
}
__device__ __forceinline__ void mbar_expect(uint32_t mbar, uint32_t tx) {
    asm volatile("mbarrier.arrive.expect_tx.shared.b64 _, [%0], %1;"
                 :: "r"(mbar), "r"(tx) : "memory");
}
__device__ __forceinline__ void bulk_g2s(uint32_t dst, const void* src,
                                         uint32_t bytes, uint32_t mbar) {
    asm volatile(
        "cp.async.bulk.shared::cluster.global.mbarrier::complete_tx::bytes "
        "[%0], [%1], %2, [%3];"
        :: "r"(dst), "l"(src), "r"(bytes), "r"(mbar) : "memory");
}
__device__ __forceinline__ void mbar_wait(uint32_t mbar, uint32_t parity) {
    asm volatile(
        "{\n\t.reg .pred P;\n"
        "WL_%=:\n\t"
        "mbarrier.try_wait.parity.acquire.cta.shared::cta.b64 P, [%0], %1, 0x989680;\n\t"
        "@P bra.uni WD_%=;\n\t"
        "bra.uni WL_%=;\n\t"
        "WD_%=:\n\t}"
        :: "r"(mbar), "r"(parity) : "memory");
}

// ---------------------------------------------------------------------------
// Kernel A: precompute PP (padded layout).  grid = (96, 14), 128 threads.
// ---------------------------------------------------------------------------
__global__ void pp_kernel(const float* __restrict__ cv,
                          const float* __restrict__ f2, const float* __restrict__ f3,
                          const float* __restrict__ f4, const float* __restrict__ f5)
{
    __shared__ float scv[64];
    const int c  = blockIdx.x;
    const int pg = blockIdx.y;
    const int j  = threadIdx.x;
    if (j < 64) scv[j] = __ldg(cv + c * 64 + j);
    __syncthreads();

    if (j < 104) {
        float s = 0.0f;
        if (j < 100) {
            const float* fp; int pl, RL;
            if (pg < 2)      { fp = f2; pl = pg;     RL = 2; }
            else if (pg < 5) { fp = f3; pl = pg - 2; RL = 3; }
            else if (pg < 9) { fp = f4; pl = pg - 5; RL = 4; }
            else             { fp = f5; pl = pg - 9; RL = 5; }
            const float4* fr = reinterpret_cast<const float4*>(fp + (j * RL + pl) * 64);
            #pragma unroll 4
            for (int q = 0; q < 16; q++) {
                const float4 fv = __ldg(fr + q);
                s += scv[4*q]   * fv.x + scv[4*q+1] * fv.y
                   + scv[4*q+2] * fv.z + scv[4*q+3] * fv.w;
            }
        }
        g_pp[(j >> 3) * 13440 + (c * 14 + pg) * 10 + (j & 7)] = s;
    }
}

// ---------------------------------------------------------------------------
// Kernel B: conv as table sums (R12 exact).  grid = 400, 256 threads,
// 2 CTAs/SM; chunks bulk-copied (one UBLKCP each), double-buffered.
// ---------------------------------------------------------------------------
#define TB1  256
#define CHUNK_U64   6720                   // 96*14*5
#define CHUNK_BYTES 53760
#define SMEMB_BYTES (2 * CHUNK_BYTES)      // 107520 B

template<int W, int PB, int BOFF>
__device__ __forceinline__ void branch_sum(const u64* __restrict__ s_pp,
                                           const int (&bix)[16],
                                           float* __restrict__ orow,
                                           int g, int j2)
{
    constexpr int L = 17 - W;
    float m0 = -1e30f, m1 = -1e30f;
    #pragma unroll
    for (int l = 0; l < L; l++) {
        u64 a = s_pp[bix[l] + PB * 5];
        #pragma unroll
        for (int p = 1; p < W; p++)
            a = fadd2(a, s_pp[bix[l + p] + (PB + p) * 5]);
        float lo, hi; unpack2(a, lo, hi);
        m0 = fmaxf(m0, lo);
        m1 = fmaxf(m1, hi);
    }
    if (g < 12 || j2 < 2) {     // chunk 12: only filters 96..99 are real
        float2 r;
        r.x = tanh_fast(m0);
        r.y = tanh_fast(m1);
        *reinterpret_cast<float2*>(orow + BOFF + g * 8 + j2 * 2) = r;
    }
}

__global__ void __launch_bounds__(TB1, 2)
conv_sum_kernel(const int* __restrict__ idxs)
{
    extern __shared__ u64 s_pp2[];
    __shared__ __align__(8) u64 mb[2];
    u64* buf[2] = { s_pp2, s_pp2 + CHUNK_U64 };
    const uint32_t sb[2] = { smem_u32(buf[0]), smem_u32(buf[1]) };
    const uint32_t mbu[2] = { smem_u32(&mb[0]), smem_u32(&mb[1]) };

    const int tid = threadIdx.x;
    const int j2  = tid & 3;
    const int token = blockIdx.x * 64 + (tid >> 2);

    int bix[16];
    {
        const int4* ip4 = reinterpret_cast<const int4*>(idxs + token * 16);
        const int4 A = __ldg(ip4 + 0), B = __ldg(ip4 + 1);
        const int4 C = __ldg(ip4 + 2), D = __ldg(ip4 + 3);
        bix[ 0] = A.x * 70 + j2; bix[ 1] = A.y * 70 + j2;
        bix[ 2] = A.z * 70 + j2; bix[ 3] = A.w * 70 + j2;
        bix[ 4] = B.x * 70 + j2; bix[ 5] = B.y * 70 + j2;
        bix[ 6] = B.z * 70 + j2; bix[ 7] = B.w * 70 + j2;
        bix[ 8] = C.x * 70 + j2; bix[ 9] = C.y * 70 + j2;
        bix[10] = C.z * 70 + j2; bix[11] = C.w * 70 + j2;
        bix[12] = D.x * 70 + j2; bix[13] = D.y * 70 + j2;
        bix[14] = D.z * 70 + j2; bix[15] = D.w * 70 + j2;
    }

    float* orow = g_outs + (size_t)token * 400;

    if (tid == 0) { mbar_init(mbu[0], 1); mbar_init(mbu[1], 1); }
    __syncthreads();

    if (tid == 0) {
        mbar_expect(mbu[0], CHUNK_BYTES);
        bulk_g2s(sb[0], g_pp, CHUNK_BYTES, mbu[0]);
    }

    int ph0 = 0, ph1 = 0;
    #pragma unroll 1
    for (int g = 0; g < 13; g++) {
        if (g < 12 && tid == 0) {
            const int b = (g + 1) & 1;
            mbar_expect(mbu[b], CHUNK_BYTES);
            bulk_g2s(sb[b], g_pp + (g + 1) * 13440, CHUNK_BYTES, mbu[b]);
        }
        if (g & 1) { mbar_wait(mbu[1], ph1); ph1 ^= 1; }
        else       { mbar_wait(mbu[0], ph0); ph0 ^= 1; }

        const u64* sp = buf[g & 1];
        branch_sum<2, 0,   0>(sp, bix, orow, g, j2);
        branch_sum<3, 2, 100>(sp, bix, orow, g, j2);
        branch_sum<4, 5, 200>(sp, bix, orow, g, j2);
        branch_sum<5, 9, 300>(sp, bix, orow, g, j2);
        __syncthreads();
    }
}

// ---------------------------------------------------------------------------
// Kernel C1: projection (R12 exact).  grid 400 (64 tok/CTA), 512 threads,
// 1 CTA/SM.  x panel bulk-copied once; w_proj streamed (cp16, pitch 44).
// ---------------------------------------------------------------------------
#define PJ_XROW 400
#define PJ_XF   (64 * PJ_XROW)             // 25600 floats
#define PJ_WP   44
#define PJ_WF   (128 * PJ_WP)              // 5632 floats per buffer
#define PJ_SMEM ((PJ_XF + 2 * PJ_WF) * 4)  // 147456 B

__global__ void __launch_bounds__(512, 1)
proj_kernel(const float* __restrict__ wp, float* __restrict__ xout)
{
    extern __shared__ float sm[];
    __shared__ __align__(8) u64 pmb;
    float* s_x = sm;                       // [64][400]
    float* w0  = s_x + PJ_XF;              // [128][44]
    float* w1  = w0 + PJ_WF;
    const uint32_t xb  = smem_u32(s_x);
    const uint32_t wb[2] = { smem_u32(w0), smem_u32(w1) };
    const uint32_t pmbu = smem_u32(&pmb);
    float* const wf[2] = { w0, w1 };

    const int tid  = threadIdx.x;
    const int c2   = tid & 63;
    const int tq   = tid >> 6;
    const int tok0 = blockIdx.x * 64;

    if (tid == 0) mbar_init(pmbu, 1);
    __syncthreads();
    if (tid == 0) {
        mbar_expect(pmbu, PJ_XF * 4);
        bulk_g2s(xb, g_outs + (size_t)tok0 * 400, PJ_XF * 4, pmbu);
    }

    auto stage_w = [&](int kc, uint32_t b) {
        #pragma unroll 1
        for (int i = tid; i < 1280; i += 512) {
            const int r = i / 10, q = i - r * 10;
            cp16(b + (uint32_t)(r * PJ_WP + 4 * q) * 4u,
                 wp + r * 400 + kc * 40 + 4 * q);
        }
    };

    stage_w(0, wb[0]);
    cp_commit();

    u64 a0[8], a1[8];
    #pragma unroll
    for (int i = 0; i < 8; i++) { a0[i] = 0ull; a1[i] = 0ull; }

    mbar_wait(pmbu, 0);

    #pragma unroll 1
    for (int kc = 0; kc < 10; kc++) {
        if (kc < 9) { stage_w(kc + 1, wb[(kc + 1) & 1]); cp_commit(); cp_wait<1>(); }
        else        { cp_wait<0>(); }
        __syncthreads();
        const float* b = wf[kc & 1];
        #pragma unroll
        for (int q = 0; q < 10; q++) {
            const ulonglong2 wa = *reinterpret_cast<const ulonglong2*>(b + c2 * PJ_WP + 4 * q);
            const ulonglong2 wv = *reinterpret_cast<const ulonglong2*>(b + (c2 + 64) * PJ_WP + 4 * q);
            #pragma unroll
            for (int i = 0; i < 8; i++) {
                const ulonglong2 xv = *reinterpret_cast<const ulonglong2*>(
                    s_x + (tq * 8 + i) * PJ_XROW + kc * 40 + 4 * q);
                ffma2(a0[i], xv.x, wa.x); ffma2(a0[i], xv.y, wa.y);
                ffma2(a1[i], xv.x, wv.x); ffma2(a1[i], xv.y, wv.y);
            }
        }
        __syncthreads();
    }

    #pragma unroll
    for (int i = 0; i < 8; i++) {
        const int t = tok0 + tq * 8 + i;
        xout[(size_t)t * 128 + c2]      = hadd2(a0[i]);
        xout[(size_t)t * 128 + c2 + 64] = hadd2(a1[i]);
    }
}

// ---------------------------------------------------------------------------
// Kernel C2: one highway layer, CHANNEL-SPLIT.  grid (148, 2), 512 threads,
// 2 CTAs/SM (32 warps).  blockIdx.y = h selects output channels h*64..h*64+63;
// resident weights = tw/gw rows for those channels (65KB, XOR-swizzled atoms,
// atom row = s*64 + c).  Single x panel (64 tokens x full 128 inputs, 33KB);
// co-resident CTA hides the staging gap.  thread = (c = tid&63 -> 1 channel;
// tq = tid>>6 -> 8 tokens).  x' = sig(g)*relu(t) + (1-sig(g))*x.
// ---------------------------------------------------------------------------
#define HW_WF   (2 * 256 * 32)             // 16384 floats (65536 B)
#define HW_XU   33                         // float4 units per token row
#define HW_XF   (64 * HW_XU * 4)           // 8448 floats
#define HW_SMEM ((HW_WF + HW_XF) * 4)      // 99328 B

__global__ void __launch_bounds__(512, 2)
hwy_kernel(const float* __restrict__ tw, const float* __restrict__ tb,
           const float* __restrict__ gw, const float* __restrict__ gb,
           const float* __restrict__ xin, float* __restrict__ xout)
{
    extern __shared__ float sm[];
    float* sw = sm;                        // [2 mats][256 atoms][32 floats]
    float* xp = sw + HW_WF;                // [64][132]
    const uint32_t swb = smem_u32(sw);
    const uint32_t xpb = smem_u32(xp);

    const int tid = threadIdx.x;
    const int c   = tid & 63;              // channel within half
    const int tq  = tid >> 6;              // token group 0..7
    const int h   = blockIdx.y;            // channel half
    const int ch  = h * 64 + c;            // global output channel

    const float tbv = __ldg(tb + ch);
    const float gbv = __ldg(gb + ch);

    // ---- stage this half's weight rows once (2 mats x 64 ch x 128 k) -----
    #pragma unroll 1
    for (int i = tid; i < 4096; i += 512) {        // quads
        const int m  = i >> 11;            // matrix 0=tw 1=gw
        const int r  = (i >> 3) & 255;     // atom row = s*64 + cc
        const int q  = i & 7;
        const int cc = r & 63;
        const int s  = r >> 6;
        const int dst = m * 2048 + r * 8 + (q ^ (cc & 7));
        const float* src = (m ? gw : tw) + (h * 64 + cc) * 128 + s * 32 + q * 4;
        cp16(swb + (uint32_t)dst * 16u, src);
    }
    cp_commit();

    const int qx = c & 7;                  // this thread's weight swizzle key

    #pragma unroll 1
    for (int b = blockIdx.x; b < 400; b += 148) {
        // ---- stage x panel (single buffer; peer CTA hides the gap) -------
        const int tok0 = b * 64;
        #pragma unroll 1
        for (int i = tid; i < 2048; i += 512) {
            const int t = i >> 5, u = i & 31;
            cp16(xpb + (uint32_t)(t * HW_XU + u) * 16u,
                 xin + (size_t)(tok0 + t) * 128 + u * 4);
        }
        cp_commit();
        cp_wait<0>();
        __syncthreads();

        u64 at[8], ag[8];
        #pragma unroll
        for (int i = 0; i < 8; i++) { at[i] = 0ull; ag[i] = 0ull; }

        #pragma unroll 1
        for (int s = 0; s < 4; s++) {
            #pragma unroll
            for (int q = 0; q < 8; q++) {
                const int qq = q ^ qx;
                const ulonglong2 wt = *reinterpret_cast<const ulonglong2*>(
                    sw + ((s * 64 + c) * 8 + qq) * 4);
                const ulonglong2 wg = *reinterpret_cast<const ulonglong2*>(
                    sw + 8192 + ((s * 64 + c) * 8 + qq) * 4);
                #pragma unroll
                for (int i = 0; i < 8; i++) {
                    const ulonglong2 xv = *reinterpret_cast<const ulonglong2*>(
                        xp + ((tq * 8 + i) * HW_XU + s * 8 + q) * 4);
                    ffma2(at[i], xv.x, wt.x); ffma2(at[i], xv.y, wt.y);
                    ffma2(ag[i], xv.x, wg.x); ffma2(ag[i], xv.y, wg.y);
                }
            }
        }

        #pragma unroll
        for (int i = 0; i < 8; i++) {
            const int t = tq * 8 + i;
            const float xo = xp[t * (HW_XU * 4) + ch];
            const float tv = fmaxf(hadd2(at[i]) + tbv, 0.0f);
            const float g  = 0.5f * tanh_fast(0.5f * (hadd2(ag[i]) + gbv)) + 0.5f;
            xout[(size_t)(tok0 + t) * 128 + ch] = g * tv + (1.0f - g) * xo;
        }

        __syncthreads();                  // x panel free for next batch
    }
}

// ---------------------------------------------------------------------------
extern "C" void kernel_launch(void* const* d_in, const int* in_sizes, int n_in,
                              void* d_out, int out_size)
{
    const int*   idxs = (const int*)  d_in[0];
    const float* cv   = (const float*)d_in[1];
    const float* f2   = (const float*)d_in[2];
    const float* f3   = (const float*)d_in[3];
    const float* f4   = (const float*)d_in[4];
    const float* f5   = (const float*)d_in[5];
    const float* wp   = (const float*)d_in[6];
    const float* tw0  = (const float*)d_in[7];
    const float* tb0  = (const float*)d_in[8];
    const float* tw1  = (const float*)d_in[9];
    const float* tb1  = (const float*)d_in[10];
    const float* gw0  = (const float*)d_in[11];
    const float* gb0  = (const float*)d_in[12];
    const float* gw1  = (const float*)d_in[13];
    const float* gb1  = (const float*)d_in[14];
    float* out = (float*)d_out;

    static bool attr_done = false;
    if (!attr_done) {
        cudaFuncSetAttribute(conv_sum_kernel,
                             cudaFuncAttributeMaxDynamicSharedMemorySize, SMEMB_BYTES);
        cudaFuncSetAttribute(proj_kernel,
                             cudaFuncAttributeMaxDynamicSharedMemorySize, PJ_SMEM);
        cudaFuncSetAttribute(hwy_kernel,
                             cudaFuncAttributeMaxDynamicSharedMemorySize, HW_SMEM);
        attr_done = true;
    }

    float* x1; cudaGetSymbolAddress((void**)&x1, g_x1);
    float* x2; cudaGetSymbolAddress((void**)&x2, g_x2);

    pp_kernel<<<dim3(96, 14), 128>>>(cv, f2, f3, f4, f5);
    conv_sum_kernel<<<NTOK / 64, TB1, SMEMB_BYTES>>>(idxs);
    proj_kernel<<<NTOK / 64, 512, PJ_SMEM>>>(wp, x1);
    hwy_kernel<<<dim3(148, 2), 512, HW_SMEM>>>(tw0, tb0, gw0, gb0, x1, x2);
    hwy_kernel<<<dim3(148, 2), 512, HW_SMEM>>>(tw1, tb1, gw1, gb1, x2, out);
}

// round 15
// speedup vs baseline: 1.3941x; 1.0174x over previous
#include <cuda_runtime.h>
#include <cstdint>

// ---------------------------------------------------------------------------
// CharacterEmbeddingLayer via vocabulary factorization + split head.
//  - conv: PP table (padded rows baked into g_pp) bulk-copied per chunk with
//    cp.async.bulk + mbarrier  (R12, measured good).
//  - proj: x-panel resident (bulk-copied), weights streamed (R12).
//  - hwy: channel-split resident weights, 2 CTAs/SM; NEW: 16 tokens/thread
//    (256 thr, 32 accs) -> crossbar:fma 0.75 (was 1.0), 2x ILP.
// NOTE: tcgen05 is unavailable — harness compiles via compute_103 virtual
// arch (no 'a' feature set); FFMA2 path is the ceiling here.
// ---------------------------------------------------------------------------

#define NTOK  25600      // 64*400 tokens

typedef unsigned long long u64;

// PP table WITH padding baked in: [13 chunks][96 chars][14 pieces][10 floats]
__device__ __align__(128) float g_pp[13 * 96 * 14 * 10];
// conv outputs: [NTOK][400]
__device__ __align__(128) float g_outs[(size_t)NTOK * 400];
// head intermediates: [NTOK][128]
__device__ __align__(128) float g_x1[(size_t)NTOK * 128];
__device__ __align__(128) float g_x2[(size_t)NTOK * 128];

// ---------------- packed fp32x2 + async helpers -----------------------------
__device__ __forceinline__ void ffma2(u64 &acc, u64 a, u64 b) {
    asm("fma.rn.f32x2 %0, %1, %2, %0;" : "+l"(acc) : "l"(a), "l"(b));
}
__device__ __forceinline__ u64 fadd2(u64 a, u64 b) {
    u64 r; asm("add.rn.f32x2 %0, %1, %2;" : "=l"(r) : "l"(a), "l"(b)); return r;
}
__device__ __forceinline__ void unpack2(u64 v, float &lo, float &hi) {
    asm("mov.b64 {%0, %1}, %2;" : "=f"(lo), "=f"(hi) : "l"(v));
}
__device__ __forceinline__ float hadd2(u64 v) {
    float lo, hi; unpack2(v, lo, hi); return lo + hi;
}
__device__ __forceinline__ float tanh_fast(float x) {
    float y;
    asm("tanh.approx.f32 %0, %1;" : "=f"(y) : "f"(x));
    return y;
}
__device__ __forceinline__ uint32_t smem_u32(const void* p) {
    return (uint32_t)__cvta_generic_to_shared(p);
}
__device__ __forceinline__ void cp16(uint32_t dst, const void* src) {
    asm volatile("cp.async.ca.shared.global [%0], [%1], 16;" :: "r"(dst), "l"(src));
}
__device__ __forceinline__ void cp_commit() {
    asm volatile("cp.async.commit_group;");
}
template<int N> __device__ __forceinline__ void cp_wait() {
    asm volatile("cp.async.wait_group %0;" :: "n"(N));
}
// ---- bulk-copy (UBLKCP) + mbarrier ----------------------------------------
__device__ __forceinline__ void mbar_init(uint32_t mbar, uint32_t cnt) {
    asm volatile("mbarrier.init.shared.b64 [%0], %1;" :: "r"(mbar), "r"(cnt) : "memory");
}
__device__ __forceinline__ void mbar_expect(uint32_t mbar, uint32_t tx) {
    asm volatile("mbarrier.arrive.expect_tx.shared.b64 _, [%0], %1;"
                 :: "r"(mbar), "r"(tx) : "memory");
}
__device__ __forceinline__ void bulk_g2s(uint32_t dst, const void* src,
                                         uint32_t bytes, uint32_t mbar) {
    asm volatile(
        "cp.async.bulk.shared::cluster.global.mbarrier::complete_tx::bytes "
        "[%0], [%1], %2, [%3];"
        :: "r"(dst), "l"(src), "r"(bytes), "r"(mbar) : "memory");
}
__device__ __forceinline__ void mbar_wait(uint32_t mbar, uint32_t parity) {
    asm volatile(
        "{\n\t.reg .pred P;\n"
        "WL_%=:\n\t"
        "mbarrier.try_wait.parity.acquire.cta.shared::cta.b64 P, [%0], %1, 0x989680;\n\t"
        "@P bra.uni WD_%=;\n\t"
        "bra.uni WL_%=;\n\t"
        "WD_%=:\n\t}"
        :: "r"(mbar), "r"(parity) : "memory");
}

// ---------------------------------------------------------------------------
// Kernel A: precompute PP (padded layout).  grid = (96, 14), 128 threads.
// ---------------------------------------------------------------------------
__global__ void pp_kernel(const float* __restrict__ cv,
                          const float* __restrict__ f2, const float* __restrict__ f3,
                          const float* __restrict__ f4, const float* __restrict__ f5)
{
    __shared__ float scv[64];
    const int c  = blockIdx.x;
    const int pg = blockIdx.y;
    const int j  = threadIdx.x;
    if (j < 64) scv[j] = __ldg(cv + c * 64 + j);
    __syncthreads();

    if (j < 104) {
        float s = 0.0f;
        if (j < 100) {
            const float* fp; int pl, RL;
            if (pg < 2)      { fp = f2; pl = pg;     RL = 2; }
            else if (pg < 5) { fp = f3; pl = pg - 2; RL = 3; }
            else if (pg < 9) { fp = f4; pl = pg - 5; RL = 4; }
            else             { fp = f5; pl = pg - 9; RL = 5; }
            const float4* fr = reinterpret_cast<const float4*>(fp + (j * RL + pl) * 64);
            #pragma unroll 4
            for (int q = 0; q < 16; q++) {
                const float4 fv = __ldg(fr + q);
                s += scv[4*q]   * fv.x + scv[4*q+1] * fv.y
                   + scv[4*q+2] * fv.z + scv[4*q+3] * fv.w;
            }
        }
        g_pp[(j >> 3) * 13440 + (c * 14 + pg) * 10 + (j & 7)] = s;
    }
}

// ---------------------------------------------------------------------------
// Kernel B: conv as table sums (R12 exact).  grid = 400, 256 threads,
// 2 CTAs/SM; chunks bulk-copied (one UBLKCP each), double-buffered.
// ---------------------------------------------------------------------------
#define TB1  256
#define CHUNK_U64   6720                   // 96*14*5
#define CHUNK_BYTES 53760
#define SMEMB_BYTES (2 * CHUNK_BYTES)      // 107520 B

template<int W, int PB, int BOFF>
__device__ __forceinline__ void branch_sum(const u64* __restrict__ s_pp,
                                           const int (&bix)[16],
                                           float* __restrict__ orow,
                                           int g, int j2)
{
    constexpr int L = 17 - W;
    float m0 = -1e30f, m1 = -1e30f;
    #pragma unroll
    for (int l = 0; l < L; l++) {
        u64 a = s_pp[bix[l] + PB * 5];
        #pragma unroll
        for (int p = 1; p < W; p++)
            a = fadd2(a, s_pp[bix[l + p] + (PB + p) * 5]);
        float lo, hi; unpack2(a, lo, hi);
        m0 = fmaxf(m0, lo);
        m1 = fmaxf(m1, hi);
    }
    if (g < 12 || j2 < 2) {     // chunk 12: only filters 96..99 are real
        float2 r;
        r.x = tanh_fast(m0);
        r.y = tanh_fast(m1);
        *reinterpret_cast<float2*>(orow + BOFF + g * 8 + j2 * 2) = r;
    }
}

__global__ void __launch_bounds__(TB1, 2)
conv_sum_kernel(const int* __restrict__ idxs)
{
    extern __shared__ u64 s_pp2[];
    __shared__ __align__(8) u64 mb[2];
    u64* buf[2] = { s_pp2, s_pp2 + CHUNK_U64 };
    const uint32_t sb[2] = { smem_u32(buf[0]), smem_u32(buf[1]) };
    const uint32_t mbu[2] = { smem_u32(&mb[0]), smem_u32(&mb[1]) };

    const int tid = threadIdx.x;
    const int j2  = tid & 3;
    const int token = blockIdx.x * 64 + (tid >> 2);

    int bix[16];
    {
        const int4* ip4 = reinterpret_cast<const int4*>(idxs + token * 16);
        const int4 A = __ldg(ip4 + 0), B = __ldg(ip4 + 1);
        const int4 C = __ldg(ip4 + 2), D = __ldg(ip4 + 3);
        bix[ 0] = A.x * 70 + j2; bix[ 1] = A.y * 70 + j2;
        bix[ 2] = A.z * 70 + j2; bix[ 3] = A.w * 70 + j2;
        bix[ 4] = B.x * 70 + j2; bix[ 5] = B.y * 70 + j2;
        bix[ 6] = B.z * 70 + j2; bix[ 7] = B.w * 70 + j2;
        bix[ 8] = C.x * 70 + j2; bix[ 9] = C.y * 70 + j2;
        bix[10] = C.z * 70 + j2; bix[11] = C.w * 70 + j2;
        bix[12] = D.x * 70 + j2; bix[13] = D.y * 70 + j2;
        bix[14] = D.z * 70 + j2; bix[15] = D.w * 70 + j2;
    }

    float* orow = g_outs + (size_t)token * 400;

    if (tid == 0) { mbar_init(mbu[0], 1); mbar_init(mbu[1], 1); }
    __syncthreads();

    if (tid == 0) {
        mbar_expect(mbu[0], CHUNK_BYTES);
        bulk_g2s(sb[0], g_pp, CHUNK_BYTES, mbu[0]);
    }

    int ph0 = 0, ph1 = 0;
    #pragma unroll 1
    for (int g = 0; g < 13; g++) {
        if (g < 12 && tid == 0) {
            const int b = (g + 1) & 1;
            mbar_expect(mbu[b], CHUNK_BYTES);
            bulk_g2s(sb[b], g_pp + (g + 1) * 13440, CHUNK_BYTES, mbu[b]);
        }
        if (g & 1) { mbar_wait(mbu[1], ph1); ph1 ^= 1; }
        else       { mbar_wait(mbu[0], ph0); ph0 ^= 1; }

        const u64* sp = buf[g & 1];
        branch_sum<2, 0,   0>(sp, bix, orow, g, j2);
        branch_sum<3, 2, 100>(sp, bix, orow, g, j2);
        branch_sum<4, 5, 200>(sp, bix, orow, g, j2);
        branch_sum<5, 9, 300>(sp, bix, orow, g, j2);
        __syncthreads();
    }
}

// ---------------------------------------------------------------------------
// Kernel C1: projection (R12 exact).  grid 400 (64 tok/CTA), 512 threads,
// 1 CTA/SM.  x panel bulk-copied once; w_proj streamed (cp16, pitch 44).
// ---------------------------------------------------------------------------
#define PJ_XROW 400
#define PJ_XF   (64 * PJ_XROW)             // 25600 floats
#define PJ_WP   44
#define PJ_WF   (128 * PJ_WP)              // 5632 floats per buffer
#define PJ_SMEM ((PJ_XF + 2 * PJ_WF) * 4)  // 147456 B

__global__ void __launch_bounds__(512, 1)
proj_kernel(const float* __restrict__ wp, float* __restrict__ xout)
{
    extern __shared__ float sm[];
    __shared__ __align__(8) u64 pmb;
    float* s_x = sm;                       // [64][400]
    float* w0  = s_x + PJ_XF;              // [128][44]
    float* w1  = w0 + PJ_WF;
    const uint32_t xb  = smem_u32(s_x);
    const uint32_t wb[2] = { smem_u32(w0), smem_u32(w1) };
    const uint32_t pmbu = smem_u32(&pmb);
    float* const wf[2] = { w0, w1 };

    const int tid  = threadIdx.x;
    const int c2   = tid & 63;
    const int tq   = tid >> 6;
    const int tok0 = blockIdx.x * 64;

    if (tid == 0) mbar_init(pmbu, 1);
    __syncthreads();
    if (tid == 0) {
        mbar_expect(pmbu, PJ_XF * 4);
        bulk_g2s(xb, g_outs + (size_t)tok0 * 400, PJ_XF * 4, pmbu);
    }

    auto stage_w = [&](int kc, uint32_t b) {
        #pragma unroll 1
        for (int i = tid; i < 1280; i += 512) {
            const int r = i / 10, q = i - r * 10;
            cp16(b + (uint32_t)(r * PJ_WP + 4 * q) * 4u,
                 wp + r * 400 + kc * 40 + 4 * q);
        }
    };

    stage_w(0, wb[0]);
    cp_commit();

    u64 a0[8], a1[8];
    #pragma unroll
    for (int i = 0; i < 8; i++) { a0[i] = 0ull; a1[i] = 0ull; }

    mbar_wait(pmbu, 0);

    #pragma unroll 1
    for (int kc = 0; kc < 10; kc++) {
        if (kc < 9) { stage_w(kc + 1, wb[(kc + 1) & 1]); cp_commit(); cp_wait<1>(); }
        else        { cp_wait<0>(); }
        __syncthreads();
        const float* b = wf[kc & 1];
        #pragma unroll
        for (int q = 0; q < 10; q++) {
            const ulonglong2 wa = *reinterpret_cast<const ulonglong2*>(b + c2 * PJ_WP + 4 * q);
            const ulonglong2 wv = *reinterpret_cast<const ulonglong2*>(b + (c2 + 64) * PJ_WP + 4 * q);
            #pragma unroll
            for (int i = 0; i < 8; i++) {
                const ulonglong2 xv = *reinterpret_cast<const ulonglong2*>(
                    s_x + (tq * 8 + i) * PJ_XROW + kc * 40 + 4 * q);
                ffma2(a0[i], xv.x, wa.x); ffma2(a0[i], xv.y, wa.y);
                ffma2(a1[i], xv.x, wv.x); ffma2(a1[i], xv.y, wv.y);
            }
        }
        __syncthreads();
    }

    #pragma unroll
    for (int i = 0; i < 8; i++) {
        const int t = tok0 + tq * 8 + i;
        xout[(size_t)t * 128 + c2]      = hadd2(a0[i]);
        xout[(size_t)t * 128 + c2 + 64] = hadd2(a1[i]);
    }
}

// ---------------------------------------------------------------------------
// Kernel C2: one highway layer, CHANNEL-SPLIT + 16-token register blocking.
// grid (148, 2), 256 threads, 2 CTAs/SM.  blockIdx.y = h -> channels
// h*64..h*64+63; resident weights (65KB, XOR-swizzled atoms).  Single x
// panel (64 tokens x 128 inputs); thread = (c = tid&63 -> 1 channel;
// tg = tid>>6 -> 16 tokens).  Per k4: 2 weight LDS (8wf) + 16 x broadcasts
// (16wf) = 24wf vs 32 fma-cyc -> crossbar:fma = 0.75, 32 independent chains.
// ---------------------------------------------------------------------------
#define HW_WF   (2 * 256 * 32)             // 16384 floats (65536 B)
#define HW_XU   33                         // float4 units per token row
#define HW_XF   (64 * HW_XU * 4)           // 8448 floats
#define HW_SMEM ((HW_WF + HW_XF) * 4)      // 99328 B

__global__ void __launch_bounds__(256, 2)
hwy_kernel(const float* __restrict__ tw, const float* __restrict__ tb,
           const float* __restrict__ gw, const float* __restrict__ gb,
           const float* __restrict__ xin, float* __restrict__ xout)
{
    extern __shared__ float sm[];
    float* sw = sm;                        // [2 mats][256 atoms][32 floats]
    float* xp = sw + HW_WF;                // [64][132]
    const uint32_t swb = smem_u32(sw);
    const uint32_t xpb = smem_u32(xp);

    const int tid = threadIdx.x;
    const int c   = tid & 63;              // channel within half
    const int tg  = tid >> 6;              // token group 0..3 (16 tokens each)
    const int h   = blockIdx.y;            // channel half
    const int ch  = h * 64 + c;            // global output channel

    const float tbv = __ldg(tb + ch);
    const float gbv = __ldg(gb + ch);

    // ---- stage this half's weight rows once (2 mats x 64 ch x 128 k) -----
    #pragma unroll 1
    for (int i = tid; i < 4096; i += 256) {        // quads
        const int m  = i >> 11;            // matrix 0=tw 1=gw
        const int r  = (i >> 3) & 255;     // atom row = s*64 + cc
        const int q  = i & 7;
        const int cc = r & 63;
        const int s  = r >> 6;
        const int dst = m * 2048 + r * 8 + (q ^ (cc & 7));
        const float* src = (m ? gw : tw) + (h * 64 + cc) * 128 + s * 32 + q * 4;
        cp16(swb + (uint32_t)dst * 16u, src);
    }
    cp_commit();

    const int qx = c & 7;                  // this thread's weight swizzle key

    #pragma unroll 1
    for (int b = blockIdx.x; b < 400; b += 148) {
        // ---- stage x panel (single buffer; peer CTA hides the gap) -------
        const int tok0 = b * 64;
        #pragma unroll 1
        for (int i = tid; i < 2048; i += 256) {
            const int t = i >> 5, u = i & 31;
            cp16(xpb + (uint32_t)(t * HW_XU + u) * 16u,
                 xin + (size_t)(tok0 + t) * 128 + u * 4);
        }
        cp_commit();
        cp_wait<0>();
        __syncthreads();

        u64 at[16], ag[16];
        #pragma unroll
        for (int i = 0; i < 16; i++) { at[i] = 0ull; ag[i] = 0ull; }

        #pragma unroll 1
        for (int s = 0; s < 4; s++) {
            #pragma unroll
            for (int q = 0; q < 8; q++) {
                const int qq = q ^ qx;
                const ulonglong2 wt = *reinterpret_cast<const ulonglong2*>(
                    sw + ((s * 64 + c) * 8 + qq) * 4);
                const ulonglong2 wg = *reinterpret_cast<const ulonglong2*>(
                    sw + 8192 + ((s * 64 + c) * 8 + qq) * 4);
                #pragma unroll
                for (int i = 0; i < 16; i++) {
                    const ulonglong2 xv = *reinterpret_cast<const ulonglong2*>(
                        xp + ((tg * 16 + i) * HW_XU + s * 8 + q) * 4);
                    ffma2(at[i], xv.x, wt.x); ffma2(at[i], xv.y, wt.y);
                    ffma2(ag[i], xv.x, wg.x); ffma2(ag[i], xv.y, wg.y);
                }
            }
        }

        #pragma unroll
        for (int i = 0; i < 16; i++) {
            const int t = tg * 16 + i;
            const float xo = xp[t * (HW_XU * 4) + ch];
            const float tv = fmaxf(hadd2(at[i]) + tbv, 0.0f);
            const float g  = 0.5f * tanh_fast(0.5f * (hadd2(ag[i]) + gbv)) + 0.5f;
            xout[(size_t)(tok0 + t) * 128 + ch] = g * tv + (1.0f - g) * xo;
        }

        __syncthreads();                  // x panel free for next batch
    }
}

// ---------------------------------------------------------------------------
extern "C" void kernel_launch(void* const* d_in, const int* in_sizes, int n_in,
                              void* d_out, int out_size)
{
    const int*   idxs = (const int*)  d_in[0];
    const float* cv   = (const float*)d_in[1];
    const float* f2   = (const float*)d_in[2];
    const float* f3   = (const float*)d_in[3];
    const float* f4   = (const float*)d_in[4];
    const float* f5   = (const float*)d_in[5];
    const float* wp   = (const float*)d_in[6];
    const float* tw0  = (const float*)d_in[7];
    const float* tb0  = (const float*)d_in[8];
    const float* tw1  = (const float*)d_in[9];
    const float* tb1  = (const float*)d_in[10];
    const float* gw0  = (const float*)d_in[11];
    const float* gb0  = (const float*)d_in[12];
    const float* gw1  = (const float*)d_in[13];
    const float* gb1  = (const float*)d_in[14];
    float* out = (float*)d_out;

    static bool attr_done = false;
    if (!attr_done) {
        cudaFuncSetAttribute(conv_sum_kernel,
                             cudaFuncAttributeMaxDynamicSharedMemorySize, SMEMB_BYTES);
        cudaFuncSetAttribute(proj_kernel,
                             cudaFuncAttributeMaxDynamicSharedMemorySize, PJ_SMEM);
        cudaFuncSetAttribute(hwy_kernel,
                             cudaFuncAttributeMaxDynamicSharedMemorySize, HW_SMEM);
        attr_done = true;
    }

    float* x1; cudaGetSymbolAddress((void**)&x1, g_x1);
    float* x2; cudaGetSymbolAddress((void**)&x2, g_x2);

    pp_kernel<<<dim3(96, 14), 128>>>(cv, f2, f3, f4, f5);
    conv_sum_kernel<<<NTOK / 64, TB1, SMEMB_BYTES>>>(idxs);
    proj_kernel<<<NTOK / 64, 512, PJ_SMEM>>>(wp, x1);
    hwy_kernel<<<dim3(148, 2), 256, HW_SMEM>>>(tw0, tb0, gw0, gb0, x1, x2);
    hwy_kernel<<<dim3(148, 2), 256, HW_SMEM>>>(tw1, tb1, gw1, gb1, x2, out);
}